// round 6
// baseline (speedup 1.0000x reference)
#include <cuda_runtime.h>
#include <cuda_fp16.h>
#include <stdint.h>
#include <math.h>

// Problem shape (fixed)
#define Bn 4
#define Ln 8192
#define Dn 1024
#define BLn (Bn * Ln)   // 32768 tokens

// ---------------------------------------------------------------------------
// Scratch (device globals)
// ---------------------------------------------------------------------------
__device__ float  g_q[(size_t)BLn * Dn];               // 128 MB
__device__ float  g_k[(size_t)BLn * Dn];               // 128 MB
__device__ __half g_xh[2][(size_t)BLn * Dn];           // 128 MB (x splits)
__device__ __half g_wh[2][2][(size_t)Dn * Dn];         // 8 MB   (Wq/Wk splits, x32)
__device__ int    g_src[BLn];
__device__ int    g_len[Bn];
__device__ double g_sumP[Bn];
__device__ int    g_nfix;
__device__ int    g_fix[BLn];

// ---------------------------------------------------------------------------
// helpers
// ---------------------------------------------------------------------------
__device__ __forceinline__ uint32_t cvta_shared_u32(const void* p) {
    uint32_t r;
    asm("{ .reg .u64 t; cvta.to.shared.u64 t, %1; cvt.u32.u64 %0, t; }"
        : "=r"(r) : "l"(p));
    return r;
}
#define LDMATRIX_X4(r0, r1, r2, r3, addr)                                  \
    asm volatile("ldmatrix.sync.aligned.m8n8.x4.shared.b16 {%0,%1,%2,%3}, [%4];" \
                 : "=r"(r0), "=r"(r1), "=r"(r2), "=r"(r3) : "r"(addr))
#define MMA16816(c0, c1, c2, c3, a0, a1, a2, a3, b0, b1)                   \
    asm volatile("mma.sync.aligned.m16n8k16.row.col.f32.f16.f16.f32 "      \
                 "{%0,%1,%2,%3}, {%4,%5,%6,%7}, {%8,%9}, {%0,%1,%2,%3};"   \
                 : "+f"(c0), "+f"(c1), "+f"(c2), "+f"(c3)                  \
                 : "r"(a0), "r"(a1), "r"(a2), "r"(a3), "r"(b0), "r"(b1))
#define CP_ASYNC16(saddr, gaddr)                                           \
    asm volatile("cp.async.cg.shared.global [%0], [%1], 16;"               \
                 :: "r"(saddr), "l"(gaddr))

// ---------------------------------------------------------------------------
// Splits: f32 -> 2 exact fp16 splits.  x unscaled; W scaled by 32 (exact,
// avoids fp16 subnormals in the W tail; cos is scale-invariant).
// ---------------------------------------------------------------------------
__global__ void split_x_kernel(const float* __restrict__ src, int n4)
{
    int i = blockIdx.x * blockDim.x + threadIdx.x;
    if (i >= n4) return;
    const float4 v = ((const float4*)src)[i];
    float a[4] = {v.x, v.y, v.z, v.w};
    unsigned short s0[4], s1[4];
    #pragma unroll
    for (int c = 0; c < 4; c++) {
        const __half h0 = __float2half_rn(a[c]);
        const float  r1 = a[c] - __half2float(h0);
        const __half h1 = __float2half_rn(r1);
        s0[c] = __half_as_ushort(h0);
        s1[c] = __half_as_ushort(h1);
    }
    uint2 u0, u1;
    u0.x = (uint32_t)s0[0] | ((uint32_t)s0[1] << 16);
    u0.y = (uint32_t)s0[2] | ((uint32_t)s0[3] << 16);
    u1.x = (uint32_t)s1[0] | ((uint32_t)s1[1] << 16);
    u1.y = (uint32_t)s1[2] | ((uint32_t)s1[3] << 16);
    ((uint2*)&g_xh[0][0])[i] = u0;
    ((uint2*)&g_xh[1][0])[i] = u1;
}

__global__ void split_w_kernel(const float* __restrict__ src, int which, int n4)
{
    int i = blockIdx.x * blockDim.x + threadIdx.x;
    if (i >= n4) return;
    if (i == 0 && which == 0) g_nfix = 0;   // reset fixup list each replay
    const float4 v = ((const float4*)src)[i];
    float a[4] = {32.0f * v.x, 32.0f * v.y, 32.0f * v.z, 32.0f * v.w};
    unsigned short s0[4], s1[4];
    #pragma unroll
    for (int c = 0; c < 4; c++) {
        const __half h0 = __float2half_rn(a[c]);
        const float  r1 = a[c] - __half2float(h0);
        const __half h1 = __float2half_rn(r1);
        s0[c] = __half_as_ushort(h0);
        s1[c] = __half_as_ushort(h1);
    }
    uint2 u0, u1;
    u0.x = (uint32_t)s0[0] | ((uint32_t)s0[1] << 16);
    u0.y = (uint32_t)s0[2] | ((uint32_t)s0[3] << 16);
    u1.x = (uint32_t)s1[0] | ((uint32_t)s1[1] << 16);
    u1.y = (uint32_t)s1[2] | ((uint32_t)s1[3] << 16);
    ((uint2*)&g_wh[which][0][0])[i] = u0;
    ((uint2*)&g_wh[which][1][0])[i] = u1;
}

// ---------------------------------------------------------------------------
// HMMA fp16x2 GEMM: C = X * W^T via 3 fp16 products (00, 01, 10).
// Tile 128x128, BK=32, 256 threads (8 warps as 2x4), warp tile 64x32.
// 4-stage cp.async pipeline, wait lag = 3 chunks, one sync per chunk.
// grid = (8 n-tiles, 256 m-tiles, 2 gemms).
// ---------------------------------------------------------------------------
#define SPLIT_BYTES 8192                   // 128 rows * 64 B
#define SIDE_BYTES  (2 * SPLIT_BYTES)      // 16384
#define STAGE_BYTES (2 * SIDE_BYTES)       // 32768 (A side + B side)
#define NSTAGE      4
#define GEMM_SMEM   (NSTAGE * STAGE_BYTES) // 131072

// swizzled byte offset of 16B unit u (0..3) in row r (64B rows)
__device__ __forceinline__ uint32_t sw_off(int r, int u) {
    return (uint32_t)(64 * r + 16 * ((u + (r >> 1)) & 3));
}

__global__ __launch_bounds__(256, 1)
void hgemm_kernel()
{
    extern __shared__ char smem[];
    const uint32_t sbase = cvta_shared_u32(smem);

    const int tid  = threadIdx.x;
    const int wid  = tid >> 5;
    const int lane = tid & 31;
    const int wm   = wid & 1;          // 0..1 : 64-row half
    const int wn   = wid >> 1;         // 0..3 : 32-col quarter
    const int tn = blockIdx.x, tm = blockIdx.y, gz = blockIdx.z;

    const int j    = lane >> 3;        // ldmatrix matrix id 0..3
    const int rlow = lane & 7;

    int rA[4], rB[2];
    #pragma unroll
    for (int mt = 0; mt < 4; mt++)
        rA[mt] = wm * 64 + mt * 16 + (j & 1) * 8 + rlow;
    #pragma unroll
    for (int g = 0; g < 2; g++)
        rB[g] = wn * 32 + g * 16 + (j & 1) * 8 + rlow;
    const int jhi = j >> 1;

    float acc[4][4][4];
    #pragma unroll
    for (int mt = 0; mt < 4; mt++)
        #pragma unroll
        for (int nt = 0; nt < 4; nt++)
            #pragma unroll
            for (int e = 0; e < 4; e++) acc[mt][nt][e] = 0.0f;

    const char* xbase = (const char*)&g_xh[0][0] + (size_t)(tm * 128) * (Dn * 2);
    const char* wbase = (const char*)&g_wh[gz][0][0] + (size_t)(tn * 128) * (Dn * 2);
    const size_t XSPL = (size_t)BLn * Dn * 2;
    const size_t WSPL = (size_t)Dn * Dn * 2;

    // loader: 8 x 16B units per thread per chunk (2048 units total)
    int l_side[8], l_s[8], l_r[8], l_u[8];
    #pragma unroll
    for (int i = 0; i < 8; i++) {
        const int v    = tid + i * 256;
        const int side = v >= 1024;
        const int w    = v & 1023;
        l_side[i] = side;
        l_s[i]    = w >> 9;
        l_r[i]    = (w >> 2) & 127;
        l_u[i]    = w & 3;
    }

    #define LOAD_CHUNK(stage, c)                                                \
    do {                                                                        \
        const uint32_t bb = sbase + (stage) * STAGE_BYTES;                      \
        _Pragma("unroll")                                                       \
        for (int i = 0; i < 8; i++) {                                           \
            const uint32_t sa = bb + l_side[i] * SIDE_BYTES +                   \
                                l_s[i] * SPLIT_BYTES + sw_off(l_r[i], l_u[i]);  \
            const char* ga = (l_side[i] ? wbase + l_s[i] * WSPL                 \
                                        : xbase + l_s[i] * XSPL) +              \
                             (size_t)l_r[i] * (Dn * 2) + (c) * 64 + l_u[i] * 16;\
            CP_ASYNC16(sa, ga);                                                 \
        }                                                                       \
        asm volatile("cp.async.commit_group;");                                 \
    } while (0)

    const int NCH = Dn / 32;   // 32 chunks
    LOAD_CHUNK(0, 0);
    LOAD_CHUNK(1, 1);
    LOAD_CHUNK(2, 2);

    for (int c = 0; c < NCH; c++) {
        if (c < NCH - 3) asm volatile("cp.async.wait_group 2;");
        else             asm volatile("cp.async.wait_group 0;");
        __syncthreads();   // stage c visible; all warps done with chunk c-1
        if (c + 3 < NCH) LOAD_CHUNK((c + 3) & (NSTAGE - 1), c + 3);

        const uint32_t aB = sbase + (c & (NSTAGE - 1)) * STAGE_BYTES;
        const uint32_t bB = aB + SIDE_BYTES;

        #pragma unroll
        for (int ks = 0; ks < 2; ks++) {
            uint32_t bfr[2][4][2];
            #pragma unroll
            for (int s = 0; s < 2; s++) {
                #pragma unroll
                for (int g = 0; g < 2; g++) {
                    uint32_t r0, r1, r2, r3;
                    const uint32_t addr = bB + s * SPLIT_BYTES + 64 * rB[g] +
                        16 * (((2 * ks + jhi) + (rB[g] >> 1)) & 3);
                    LDMATRIX_X4(r0, r1, r2, r3, addr);
                    bfr[s][2 * g + 0][0] = r0; bfr[s][2 * g + 0][1] = r2;
                    bfr[s][2 * g + 1][0] = r1; bfr[s][2 * g + 1][1] = r3;
                }
            }
            #pragma unroll
            for (int pa = 0; pa < 2; pa++) {
                uint32_t afr[4][4];
                #pragma unroll
                for (int mt = 0; mt < 4; mt++) {
                    const uint32_t addr = aB + pa * SPLIT_BYTES + 64 * rA[mt] +
                        16 * (((2 * ks + jhi) + (rA[mt] >> 1)) & 3);
                    LDMATRIX_X4(afr[mt][0], afr[mt][1], afr[mt][2], afr[mt][3], addr);
                }
                const int npb = (pa == 0) ? 2 : 1;   // products 00, 01, 10
                for (int pb = 0; pb < npb; pb++) {
                    #pragma unroll
                    for (int mt = 0; mt < 4; mt++)
                        #pragma unroll
                        for (int nt = 0; nt < 4; nt++)
                            MMA16816(acc[mt][nt][0], acc[mt][nt][1],
                                     acc[mt][nt][2], acc[mt][nt][3],
                                     afr[mt][0], afr[mt][1], afr[mt][2], afr[mt][3],
                                     bfr[pb][nt][0], bfr[pb][nt][1]);
                }
            }
        }
    }

    // epilogue (values are 32x the true q/k; cos is scale-invariant)
    float* C = (gz == 0) ? g_q : g_k;
    const int rowb = tm * 128 + wm * 64 + (lane >> 2);
    const int colb = tn * 128 + wn * 32 + 2 * (lane & 3);
    #pragma unroll
    for (int mt = 0; mt < 4; mt++) {
        #pragma unroll
        for (int nt = 0; nt < 4; nt++) {
            const size_t r0 = (size_t)(rowb + mt * 16) * Dn + colb + nt * 8;
            *(float2*)&C[r0]          = make_float2(acc[mt][nt][0], acc[mt][nt][1]);
            *(float2*)&C[r0 + 8 * Dn] = make_float2(acc[mt][nt][2], acc[mt][nt][3]);
        }
    }
    #undef LOAD_CHUNK
}

// ---------------------------------------------------------------------------
// Per-token props: p, b (fp64 reductions); flag borderline |cos| for fixup.
// ---------------------------------------------------------------------------
__global__ void props_kernel(float* __restrict__ out_p, float* __restrict__ out_b)
{
    const int t   = blockIdx.x;
    const int l   = t & (Ln - 1);
    const int tid = threadIdx.x;

    if (l == 0) {
        if (tid == 0) { out_p[t] = 1.0f; out_b[t] = 1.0f; }
        return;
    }
    const float4* qr = (const float4*)(g_q + (size_t)t * Dn);
    const float4* kr = (const float4*)(g_k + (size_t)(t - 1) * Dn);

    double sq = 0.0, sk = 0.0, sp = 0.0;
    #pragma unroll
    for (int it = 0; it < 2; it++) {
        const float4 qv = qr[tid + it * 128];
        const float4 kv = kr[tid + it * 128];
        sq += (double)qv.x * qv.x + (double)qv.y * qv.y +
              (double)qv.z * qv.z + (double)qv.w * qv.w;
        sk += (double)kv.x * kv.x + (double)kv.y * kv.y +
              (double)kv.z * kv.z + (double)kv.w * kv.w;
        sp += (double)qv.x * kv.x + (double)qv.y * kv.y +
              (double)qv.z * kv.z + (double)qv.w * kv.w;
    }
    #pragma unroll
    for (int o = 16; o > 0; o >>= 1) {
        sq += __shfl_down_sync(0xffffffffu, sq, o);
        sk += __shfl_down_sync(0xffffffffu, sk, o);
        sp += __shfl_down_sync(0xffffffffu, sp, o);
    }
    __shared__ double sh[3][4];
    const int wid = tid >> 5, lane = tid & 31;
    if (lane == 0) { sh[0][wid] = sq; sh[1][wid] = sk; sh[2][wid] = sp; }
    __syncthreads();
    if (tid == 0) {
        const double SQ = sh[0][0] + sh[0][1] + sh[0][2] + sh[0][3];
        const double SK = sh[1][0] + sh[1][1] + sh[1][2] + sh[1][3];
        const double SP = sh[2][0] + sh[2][1] + sh[2][2] + sh[2][3];
        const float nq = fmaxf(sqrtf((float)SQ), 1e-12f);
        const float nk = fmaxf(sqrtf((float)SK), 1e-12f);
        const float cs = (float)SP / (nq * nk);
        const float pv = 0.5f * (1.0f - cs);
        out_p[t] = pv;
        out_b[t] = (pv >= 0.5f) ? 1.0f : 0.0f;
        if (fabsf(cs) < 2e-5f) {
            const int ix = atomicAdd(&g_nfix, 1);
            if (ix < BLn) g_fix[ix] = t;
        }
    }
}

// ---------------------------------------------------------------------------
// Fixup: exact recompute of cos for borderline tokens; overwrite b.
// ---------------------------------------------------------------------------
__global__ void fixup_kernel(const float* __restrict__ x,
                             const float* __restrict__ Wq,
                             const float* __restrict__ Wk,
                             float* __restrict__ out_b)
{
    __shared__ float  xs[Dn], xp[Dn];
    __shared__ double sh[3][8];
    const int tid  = threadIdx.x;          // 256
    const int lane = tid & 31, wrp = tid >> 5;
    const int nf = g_nfix < BLn ? g_nfix : BLn;

    for (int it = blockIdx.x; it < nf; it += gridDim.x) {
        const int t = g_fix[it];
        for (int d = tid; d < Dn; d += 256) {
            xs[d] = x[(size_t)t * Dn + d];
            xp[d] = x[(size_t)(t - 1) * Dn + d];
        }
        __syncthreads();

        double sq = 0.0, sk = 0.0, sp = 0.0;
        for (int e = tid; e < Dn; e += 256) {
            const float* wq = Wq + (size_t)e * Dn;
            const float* wk = Wk + (size_t)e * Dn;
            double qd = 0.0, kd = 0.0;
            for (int d0 = 0; d0 < Dn; d0 += 4) {
                float q4 = xs[d0] * wq[d0];
                q4 = fmaf(xs[d0 + 1], wq[d0 + 1], q4);
                q4 = fmaf(xs[d0 + 2], wq[d0 + 2], q4);
                q4 = fmaf(xs[d0 + 3], wq[d0 + 3], q4);
                float k4 = xp[d0] * wk[d0];
                k4 = fmaf(xp[d0 + 1], wk[d0 + 1], k4);
                k4 = fmaf(xp[d0 + 2], wk[d0 + 2], k4);
                k4 = fmaf(xp[d0 + 3], wk[d0 + 3], k4);
                qd += (double)q4;
                kd += (double)k4;
            }
            sq += qd * qd;
            sk += kd * kd;
            sp += qd * kd;
        }
        #pragma unroll
        for (int o = 16; o > 0; o >>= 1) {
            sq += __shfl_down_sync(0xffffffffu, sq, o);
            sk += __shfl_down_sync(0xffffffffu, sk, o);
            sp += __shfl_down_sync(0xffffffffu, sp, o);
        }
        if (lane == 0) { sh[0][wrp] = sq; sh[1][wrp] = sk; sh[2][wrp] = sp; }
        __syncthreads();
        if (tid == 0) {
            double SQ = 0, SK = 0, SP = 0;
            for (int w = 0; w < 8; w++) { SQ += sh[0][w]; SK += sh[1][w]; SP += sh[2][w]; }
            const double cs = SP / sqrt(SQ * SK);
            out_b[t] = (cs <= 0.0) ? 1.0f : 0.0f;
        }
        __syncthreads();
    }
}

// ---------------------------------------------------------------------------
// Per-batch scan of b
// ---------------------------------------------------------------------------
__global__ void scan_kernel(const float* __restrict__ p_arr,
                            const float* __restrict__ b_arr,
                            float* __restrict__ P_down,
                            float* __restrict__ out_len)
{
    const int batch = blockIdx.x;
    const int tid   = threadIdx.x;
    const float* bb = b_arr + batch * Ln;
    const float* pp = p_arr + batch * Ln;
    const int base  = tid * 32;

    int    cnt  = 0;
    double sump = 0.0;
    #pragma unroll 8
    for (int jj = 0; jj < 32; jj++) {
        const float bv = bb[base + jj];
        cnt  += (bv > 0.5f) ? 1 : 0;
        sump += (double)pp[base + jj];
    }
    const int lane = tid & 31, wid = tid >> 5;
    int v = cnt;
    #pragma unroll
    for (int o = 1; o < 32; o <<= 1) {
        const int n = __shfl_up_sync(0xffffffffu, v, o);
        if (lane >= o) v += n;
    }
    __shared__ int wsum[8], woff[8], stotal;
    if (lane == 31) wsum[wid] = v;
    __syncthreads();
    if (tid == 0) {
        int s = 0;
        for (int w = 0; w < 8; w++) { woff[w] = s; s += wsum[w]; }
        stotal = s;
    }
    __syncthreads();

    int slot = woff[wid] + v - cnt;
    const int total = stotal;

    for (int jj = 0; jj < 32; jj++) {
        const float bv = bb[base + jj];
        if (bv > 0.5f) {
            const int l = base + jj;
            g_src[batch * Ln + slot]  = l;
            P_down[batch * Ln + slot] = pp[l];
            slot++;
        }
    }
    for (int s = total + tid; s < Ln; s += 256)
        P_down[batch * Ln + s] = 0.0f;

    #pragma unroll
    for (int o = 16; o > 0; o >>= 1)
        sump += __shfl_down_sync(0xffffffffu, sump, o);
    __shared__ double psh[8];
    if (lane == 0) psh[wid] = sump;
    __syncthreads();
    if (tid == 0) {
        double s = 0.0;
        for (int w = 0; w < 8; w++) s += psh[w];
        g_sumP[batch]  = s;
        g_len[batch]   = total;
        out_len[batch] = (float)total;
    }
}

// ---------------------------------------------------------------------------
// Gather x_down
// ---------------------------------------------------------------------------
__global__ void gather_kernel(const float* __restrict__ x, float* __restrict__ x_down)
{
    const int row   = blockIdx.x;
    const int batch = row >> 13;
    const int jj    = row & (Ln - 1);
    const int tid   = threadIdx.x;

    float4* dst = (float4*)(x_down + (size_t)row * Dn);
    if (jj < g_len[batch]) {
        const int src = g_src[row];
        const float4* s = (const float4*)(x + (size_t)(batch * Ln + src) * Dn);
        dst[tid] = s[tid];
    } else {
        dst[tid] = make_float4(0.f, 0.f, 0.f, 0.f);
    }
}

__global__ void finalize_kernel(float* __restrict__ o_loss)
{
    double sb = 0.0, sp = 0.0;
    for (int i = 0; i < Bn; i++) { sb += (double)g_len[i]; sp += g_sumP[i]; }
    const double F = sb / (double)BLn;
    const double G = sp / (double)BLn;
    const double N = 6.0;
    o_loss[0] = (float)(N / (N - 1.0) * ((N - 1.0) * F * G + (1.0 - F) * (1.0 - G)));
}

// ---------------------------------------------------------------------------
// Launch. Output layout (f32): x_down | P_down | b | p | lengths | ratio_loss
// ---------------------------------------------------------------------------
extern "C" void kernel_launch(void* const* d_in, const int* in_sizes, int n_in,
                              void* d_out, int out_size)
{
    const float* x  = (const float*)d_in[0];
    const float* Wq = (const float*)d_in[1];
    const float* Wk = (const float*)d_in[2];

    float* out    = (float*)d_out;
    float* o_xd   = out;
    float* o_P    = out + (size_t)BLn * Dn;
    float* o_b    = o_P + BLn;
    float* o_p    = o_b + BLn;
    float* o_len  = o_p + BLn;
    float* o_loss = o_len + Bn;

    cudaFuncSetAttribute(hgemm_kernel,
                         cudaFuncAttributeMaxDynamicSharedMemorySize, GEMM_SMEM);

    split_w_kernel<<<(Dn * Dn / 4 + 255) / 256, 256>>>(Wq, 0, Dn * Dn / 4);
    split_w_kernel<<<(Dn * Dn / 4 + 255) / 256, 256>>>(Wk, 1, Dn * Dn / 4);
    split_x_kernel<<<(BLn * Dn / 4 + 255) / 256, 256>>>(x, BLn * Dn / 4);

    hgemm_kernel<<<dim3(8, 256, 2), 256, GEMM_SMEM>>>();

    props_kernel<<<BLn, 128>>>(o_p, o_b);
    fixup_kernel<<<64, 256>>>(x, Wq, Wk, o_b);
    scan_kernel<<<Bn, 256>>>(o_p, o_b, o_P, o_len);
    gather_kernel<<<BLn, 256>>>(x, o_xd);
    finalize_kernel<<<1, 1>>>(o_loss);
}

// round 7
// speedup vs baseline: 1.0719x; 1.0719x over previous
#include <cuda_runtime.h>
#include <cuda_bf16.h>
#include <stdint.h>
#include <math.h>

// Problem shape (fixed)
#define Bn 4
#define Ln 8192
#define Dn 1024
#define BLn (Bn * Ln)   // 32768 tokens

// ---------------------------------------------------------------------------
// Scratch (device globals)
// ---------------------------------------------------------------------------
__device__ float  g_q[(size_t)BLn * Dn];                 // 128 MB
__device__ float  g_k[(size_t)BLn * Dn];                 // 128 MB
__device__ __nv_bfloat16 g_xh[2][(size_t)BLn * Dn];     // 128 MB (x splits)
__device__ __nv_bfloat16 g_wh[2][2][(size_t)Dn * Dn];   // 8 MB   (Wq/Wk splits)
__device__ int    g_src[BLn];
__device__ int    g_len[Bn];
__device__ double g_sumP[Bn];
__device__ int    g_nfix;
__device__ int    g_fix[BLn];

// ---------------------------------------------------------------------------
// helpers
// ---------------------------------------------------------------------------
__device__ __forceinline__ uint32_t cvta_shared_u32(const void* p) {
    uint32_t r;
    asm("{ .reg .u64 t; cvta.to.shared.u64 t, %1; cvt.u32.u64 %0, t; }"
        : "=r"(r) : "l"(p));
    return r;
}
#define LDMATRIX_X4(r0, r1, r2, r3, addr)                                  \
    asm volatile("ldmatrix.sync.aligned.m8n8.x4.shared.b16 {%0,%1,%2,%3}, [%4];" \
                 : "=r"(r0), "=r"(r1), "=r"(r2), "=r"(r3) : "r"(addr))
#define MMA16816(c0, c1, c2, c3, a0, a1, a2, a3, b0, b1)                   \
    asm volatile("mma.sync.aligned.m16n8k16.row.col.f32.bf16.bf16.f32 "    \
                 "{%0,%1,%2,%3}, {%4,%5,%6,%7}, {%8,%9}, {%0,%1,%2,%3};"   \
                 : "+f"(c0), "+f"(c1), "+f"(c2), "+f"(c3)                  \
                 : "r"(a0), "r"(a1), "r"(a2), "r"(a3), "r"(b0), "r"(b1))
#define CP_ASYNC16(saddr, gaddr)                                           \
    asm volatile("cp.async.cg.shared.global [%0], [%1], 16;"               \
                 :: "r"(saddr), "l"(gaddr))

// ---------------------------------------------------------------------------
// Splits: f32 -> 2 exact bf16 splits (h0 + h1; dropped tail ~2^-17 rel).
// ---------------------------------------------------------------------------
__global__ void split_x_kernel(const float* __restrict__ src, int n4)
{
    int i = blockIdx.x * blockDim.x + threadIdx.x;
    if (i >= n4) return;
    const float4 v = ((const float4*)src)[i];
    float a[4] = {v.x, v.y, v.z, v.w};
    unsigned short s0[4], s1[4];
    #pragma unroll
    for (int c = 0; c < 4; c++) {
        const __nv_bfloat16 h0 = __float2bfloat16_rn(a[c]);
        const float r1 = a[c] - __bfloat162float(h0);
        const __nv_bfloat16 h1 = __float2bfloat16_rn(r1);
        s0[c] = __bfloat16_as_ushort(h0);
        s1[c] = __bfloat16_as_ushort(h1);
    }
    uint2 u0, u1;
    u0.x = (uint32_t)s0[0] | ((uint32_t)s0[1] << 16);
    u0.y = (uint32_t)s0[2] | ((uint32_t)s0[3] << 16);
    u1.x = (uint32_t)s1[0] | ((uint32_t)s1[1] << 16);
    u1.y = (uint32_t)s1[2] | ((uint32_t)s1[3] << 16);
    ((uint2*)&g_xh[0][0])[i] = u0;
    ((uint2*)&g_xh[1][0])[i] = u1;
}

__global__ void split_w_kernel(const float* __restrict__ src, int which, int n4)
{
    int i = blockIdx.x * blockDim.x + threadIdx.x;
    if (i >= n4) return;
    if (i == 0 && which == 0) g_nfix = 0;   // reset fixup list each replay
    const float4 v = ((const float4*)src)[i];
    float a[4] = {v.x, v.y, v.z, v.w};
    unsigned short s0[4], s1[4];
    #pragma unroll
    for (int c = 0; c < 4; c++) {
        const __nv_bfloat16 h0 = __float2bfloat16_rn(a[c]);
        const float r1 = a[c] - __bfloat162float(h0);
        const __nv_bfloat16 h1 = __float2bfloat16_rn(r1);
        s0[c] = __bfloat16_as_ushort(h0);
        s1[c] = __bfloat16_as_ushort(h1);
    }
    uint2 u0, u1;
    u0.x = (uint32_t)s0[0] | ((uint32_t)s0[1] << 16);
    u0.y = (uint32_t)s0[2] | ((uint32_t)s0[3] << 16);
    u1.x = (uint32_t)s1[0] | ((uint32_t)s1[1] << 16);
    u1.y = (uint32_t)s1[2] | ((uint32_t)s1[3] << 16);
    ((uint2*)&g_wh[which][0][0])[i] = u0;
    ((uint2*)&g_wh[which][1][0])[i] = u1;
}

// ---------------------------------------------------------------------------
// HMMA bf16x2 GEMM: C = X * W^T via 3 bf16 products (00, 01, 10).
// Tile 128x128, BK=32, 256 threads (8 warps as 2x4), warp tile 64x32.
// R4 skeleton: 2 smem buffers, loads issued then wait_group 1, 2 syncs/chunk.
// grid = (8 n-tiles, 256 m-tiles, 2 gemms).
// ---------------------------------------------------------------------------
#define SPLIT_BYTES 8192                   // 128 rows * 64 B
#define SIDE_BYTES  (2 * SPLIT_BYTES)      // 16384
#define BUF_BYTES   (2 * SIDE_BYTES)       // 32768 (A side + B side)
#define GEMM_SMEM   (2 * BUF_BYTES)        // 65536

// swizzled byte offset of 16B unit u (0..3) in row r (64B rows)
__device__ __forceinline__ uint32_t sw_off(int r, int u) {
    return (uint32_t)(64 * r + 16 * ((u + (r >> 1)) & 3));
}

__global__ __launch_bounds__(256, 2)
void hgemm_kernel()
{
    extern __shared__ char smem[];
    const uint32_t sbase = cvta_shared_u32(smem);

    const int tid  = threadIdx.x;
    const int wid  = tid >> 5;
    const int lane = tid & 31;
    const int wm   = wid & 1;          // 0..1 : 64-row half
    const int wn   = wid >> 1;         // 0..3 : 32-col quarter
    const int tn = blockIdx.x, tm = blockIdx.y, gz = blockIdx.z;

    const int j    = lane >> 3;        // ldmatrix matrix id 0..3
    const int rlow = lane & 7;

    int rA[4], rB[2];
    #pragma unroll
    for (int mt = 0; mt < 4; mt++)
        rA[mt] = wm * 64 + mt * 16 + (j & 1) * 8 + rlow;
    #pragma unroll
    for (int g = 0; g < 2; g++)
        rB[g] = wn * 32 + g * 16 + (j & 1) * 8 + rlow;
    const int jhi = j >> 1;

    float acc[4][4][4];
    #pragma unroll
    for (int mt = 0; mt < 4; mt++)
        #pragma unroll
        for (int nt = 0; nt < 4; nt++)
            #pragma unroll
            for (int e = 0; e < 4; e++) acc[mt][nt][e] = 0.0f;

    const char* xbase = (const char*)&g_xh[0][0] + (size_t)(tm * 128) * (Dn * 2);
    const char* wbase = (const char*)&g_wh[gz][0][0] + (size_t)(tn * 128) * (Dn * 2);
    const size_t XSPL = (size_t)BLn * Dn * 2;
    const size_t WSPL = (size_t)Dn * Dn * 2;

    // loader: 8 x 16B units per thread per chunk (2048 units total)
    int l_side[8], l_s[8], l_r[8], l_u[8];
    #pragma unroll
    for (int i = 0; i < 8; i++) {
        const int v    = tid + i * 256;
        const int side = v >= 1024;
        const int w    = v & 1023;
        l_side[i] = side;
        l_s[i]    = w >> 9;
        l_r[i]    = (w >> 2) & 127;
        l_u[i]    = w & 3;
    }

    #define LOAD_CHUNK(buf, c)                                                  \
    do {                                                                        \
        const uint32_t bb = sbase + (buf) * BUF_BYTES;                          \
        _Pragma("unroll")                                                       \
        for (int i = 0; i < 8; i++) {                                           \
            const uint32_t sa = bb + l_side[i] * SIDE_BYTES +                   \
                                l_s[i] * SPLIT_BYTES + sw_off(l_r[i], l_u[i]);  \
            const char* ga = (l_side[i] ? wbase + l_s[i] * WSPL                 \
                                        : xbase + l_s[i] * XSPL) +              \
                             (size_t)l_r[i] * (Dn * 2) + (c) * 64 + l_u[i] * 16;\
            CP_ASYNC16(sa, ga);                                                 \
        }                                                                       \
        asm volatile("cp.async.commit_group;");                                 \
    } while (0)

    const int NCH = Dn / 32;   // 32 chunks
    LOAD_CHUNK(0, 0);

    for (int c = 0; c < NCH; c++) {
        const int buf = c & 1;
        if (c + 1 < NCH) {
            LOAD_CHUNK(buf ^ 1, c + 1);
            asm volatile("cp.async.wait_group 1;");
        } else {
            asm volatile("cp.async.wait_group 0;");
        }
        __syncthreads();

        const uint32_t aB = sbase + buf * BUF_BYTES;
        const uint32_t bB = aB + SIDE_BYTES;

        #pragma unroll
        for (int ks = 0; ks < 2; ks++) {
            uint32_t bfr[2][4][2];
            #pragma unroll
            for (int s = 0; s < 2; s++) {
                #pragma unroll
                for (int g = 0; g < 2; g++) {
                    uint32_t r0, r1, r2, r3;
                    const uint32_t addr = bB + s * SPLIT_BYTES + 64 * rB[g] +
                        16 * (((2 * ks + jhi) + (rB[g] >> 1)) & 3);
                    LDMATRIX_X4(r0, r1, r2, r3, addr);
                    bfr[s][2 * g + 0][0] = r0; bfr[s][2 * g + 0][1] = r2;
                    bfr[s][2 * g + 1][0] = r1; bfr[s][2 * g + 1][1] = r3;
                }
            }
            #pragma unroll
            for (int pa = 0; pa < 2; pa++) {
                uint32_t afr[4][4];
                #pragma unroll
                for (int mt = 0; mt < 4; mt++) {
                    const uint32_t addr = aB + pa * SPLIT_BYTES + 64 * rA[mt] +
                        16 * (((2 * ks + jhi) + (rA[mt] >> 1)) & 3);
                    LDMATRIX_X4(afr[mt][0], afr[mt][1], afr[mt][2], afr[mt][3], addr);
                }
                const int npb = (pa == 0) ? 2 : 1;   // products 00, 01, 10
                for (int pb = 0; pb < npb; pb++) {
                    #pragma unroll
                    for (int mt = 0; mt < 4; mt++)
                        #pragma unroll
                        for (int nt = 0; nt < 4; nt++)
                            MMA16816(acc[mt][nt][0], acc[mt][nt][1],
                                     acc[mt][nt][2], acc[mt][nt][3],
                                     afr[mt][0], afr[mt][1], afr[mt][2], afr[mt][3],
                                     bfr[pb][nt][0], bfr[pb][nt][1]);
                }
            }
        }
        __syncthreads();
    }

    // epilogue
    float* C = (gz == 0) ? g_q : g_k;
    const int rowb = tm * 128 + wm * 64 + (lane >> 2);
    const int colb = tn * 128 + wn * 32 + 2 * (lane & 3);
    #pragma unroll
    for (int mt = 0; mt < 4; mt++) {
        #pragma unroll
        for (int nt = 0; nt < 4; nt++) {
            const size_t r0 = (size_t)(rowb + mt * 16) * Dn + colb + nt * 8;
            *(float2*)&C[r0]          = make_float2(acc[mt][nt][0], acc[mt][nt][1]);
            *(float2*)&C[r0 + 8 * Dn] = make_float2(acc[mt][nt][2], acc[mt][nt][3]);
        }
    }
    #undef LOAD_CHUNK
}

// ---------------------------------------------------------------------------
// Per-token props: p, b (fp64 reductions); flag borderline |cos| for fixup.
// ---------------------------------------------------------------------------
__global__ void props_kernel(float* __restrict__ out_p, float* __restrict__ out_b)
{
    const int t   = blockIdx.x;
    const int l   = t & (Ln - 1);
    const int tid = threadIdx.x;

    if (l == 0) {
        if (tid == 0) { out_p[t] = 1.0f; out_b[t] = 1.0f; }
        return;
    }
    const float4* qr = (const float4*)(g_q + (size_t)t * Dn);
    const float4* kr = (const float4*)(g_k + (size_t)(t - 1) * Dn);

    double sq = 0.0, sk = 0.0, sp = 0.0;
    #pragma unroll
    for (int it = 0; it < 2; it++) {
        const float4 qv = qr[tid + it * 128];
        const float4 kv = kr[tid + it * 128];
        sq += (double)qv.x * qv.x + (double)qv.y * qv.y +
              (double)qv.z * qv.z + (double)qv.w * qv.w;
        sk += (double)kv.x * kv.x + (double)kv.y * kv.y +
              (double)kv.z * kv.z + (double)kv.w * kv.w;
        sp += (double)qv.x * kv.x + (double)qv.y * kv.y +
              (double)qv.z * kv.z + (double)qv.w * kv.w;
    }
    #pragma unroll
    for (int o = 16; o > 0; o >>= 1) {
        sq += __shfl_down_sync(0xffffffffu, sq, o);
        sk += __shfl_down_sync(0xffffffffu, sk, o);
        sp += __shfl_down_sync(0xffffffffu, sp, o);
    }
    __shared__ double sh[3][4];
    const int wid = tid >> 5, lane = tid & 31;
    if (lane == 0) { sh[0][wid] = sq; sh[1][wid] = sk; sh[2][wid] = sp; }
    __syncthreads();
    if (tid == 0) {
        const double SQ = sh[0][0] + sh[0][1] + sh[0][2] + sh[0][3];
        const double SK = sh[1][0] + sh[1][1] + sh[1][2] + sh[1][3];
        const double SP = sh[2][0] + sh[2][1] + sh[2][2] + sh[2][3];
        const float nq = fmaxf(sqrtf((float)SQ), 1e-12f);
        const float nk = fmaxf(sqrtf((float)SK), 1e-12f);
        const float cs = (float)SP / (nq * nk);
        const float pv = 0.5f * (1.0f - cs);
        out_p[t] = pv;
        out_b[t] = (pv >= 0.5f) ? 1.0f : 0.0f;
        if (fabsf(cs) < 2e-5f) {
            const int ix = atomicAdd(&g_nfix, 1);
            if (ix < BLn) g_fix[ix] = t;
        }
    }
}

// ---------------------------------------------------------------------------
// Fixup: exact recompute of cos for borderline tokens; overwrite b.
// ---------------------------------------------------------------------------
__global__ void fixup_kernel(const float* __restrict__ x,
                             const float* __restrict__ Wq,
                             const float* __restrict__ Wk,
                             float* __restrict__ out_b)
{
    __shared__ float  xs[Dn], xp[Dn];
    __shared__ double sh[3][8];
    const int tid  = threadIdx.x;          // 256
    const int lane = tid & 31, wrp = tid >> 5;
    const int nf = g_nfix < BLn ? g_nfix : BLn;

    for (int it = blockIdx.x; it < nf; it += gridDim.x) {
        const int t = g_fix[it];
        for (int d = tid; d < Dn; d += 256) {
            xs[d] = x[(size_t)t * Dn + d];
            xp[d] = x[(size_t)(t - 1) * Dn + d];
        }
        __syncthreads();

        double sq = 0.0, sk = 0.0, sp = 0.0;
        for (int e = tid; e < Dn; e += 256) {
            const float* wq = Wq + (size_t)e * Dn;
            const float* wk = Wk + (size_t)e * Dn;
            double qd = 0.0, kd = 0.0;
            for (int d0 = 0; d0 < Dn; d0 += 4) {
                float q4 = xs[d0] * wq[d0];
                q4 = fmaf(xs[d0 + 1], wq[d0 + 1], q4);
                q4 = fmaf(xs[d0 + 2], wq[d0 + 2], q4);
                q4 = fmaf(xs[d0 + 3], wq[d0 + 3], q4);
                float k4 = xp[d0] * wk[d0];
                k4 = fmaf(xp[d0 + 1], wk[d0 + 1], k4);
                k4 = fmaf(xp[d0 + 2], wk[d0 + 2], k4);
                k4 = fmaf(xp[d0 + 3], wk[d0 + 3], k4);
                qd += (double)q4;
                kd += (double)k4;
            }
            sq += qd * qd;
            sk += kd * kd;
            sp += qd * kd;
        }
        #pragma unroll
        for (int o = 16; o > 0; o >>= 1) {
            sq += __shfl_down_sync(0xffffffffu, sq, o);
            sk += __shfl_down_sync(0xffffffffu, sk, o);
            sp += __shfl_down_sync(0xffffffffu, sp, o);
        }
        if (lane == 0) { sh[0][wrp] = sq; sh[1][wrp] = sk; sh[2][wrp] = sp; }
        __syncthreads();
        if (tid == 0) {
            double SQ = 0, SK = 0, SP = 0;
            for (int w = 0; w < 8; w++) { SQ += sh[0][w]; SK += sh[1][w]; SP += sh[2][w]; }
            const double cs = SP / sqrt(SQ * SK);
            out_b[t] = (cs <= 0.0) ? 1.0f : 0.0f;
        }
        __syncthreads();
    }
}

// ---------------------------------------------------------------------------
// Per-batch scan of b
// ---------------------------------------------------------------------------
__global__ void scan_kernel(const float* __restrict__ p_arr,
                            const float* __restrict__ b_arr,
                            float* __restrict__ P_down,
                            float* __restrict__ out_len)
{
    const int batch = blockIdx.x;
    const int tid   = threadIdx.x;
    const float* bb = b_arr + batch * Ln;
    const float* pp = p_arr + batch * Ln;
    const int base  = tid * 32;

    int    cnt  = 0;
    double sump = 0.0;
    #pragma unroll 8
    for (int jj = 0; jj < 32; jj++) {
        const float bv = bb[base + jj];
        cnt  += (bv > 0.5f) ? 1 : 0;
        sump += (double)pp[base + jj];
    }
    const int lane = tid & 31, wid = tid >> 5;
    int v = cnt;
    #pragma unroll
    for (int o = 1; o < 32; o <<= 1) {
        const int n = __shfl_up_sync(0xffffffffu, v, o);
        if (lane >= o) v += n;
    }
    __shared__ int wsum[8], woff[8], stotal;
    if (lane == 31) wsum[wid] = v;
    __syncthreads();
    if (tid == 0) {
        int s = 0;
        for (int w = 0; w < 8; w++) { woff[w] = s; s += wsum[w]; }
        stotal = s;
    }
    __syncthreads();

    int slot = woff[wid] + v - cnt;
    const int total = stotal;

    for (int jj = 0; jj < 32; jj++) {
        const float bv = bb[base + jj];
        if (bv > 0.5f) {
            const int l = base + jj;
            g_src[batch * Ln + slot]  = l;
            P_down[batch * Ln + slot] = pp[l];
            slot++;
        }
    }
    for (int s = total + tid; s < Ln; s += 256)
        P_down[batch * Ln + s] = 0.0f;

    #pragma unroll
    for (int o = 16; o > 0; o >>= 1)
        sump += __shfl_down_sync(0xffffffffu, sump, o);
    __shared__ double psh[8];
    if (lane == 0) psh[wid] = sump;
    __syncthreads();
    if (tid == 0) {
        double s = 0.0;
        for (int w = 0; w < 8; w++) s += psh[w];
        g_sumP[batch]  = s;
        g_len[batch]   = total;
        out_len[batch] = (float)total;
    }
}

// ---------------------------------------------------------------------------
// Gather x_down
// ---------------------------------------------------------------------------
__global__ void gather_kernel(const float* __restrict__ x, float* __restrict__ x_down)
{
    const int row   = blockIdx.x;
    const int batch = row >> 13;
    const int jj    = row & (Ln - 1);
    const int tid   = threadIdx.x;

    float4* dst = (float4*)(x_down + (size_t)row * Dn);
    if (jj < g_len[batch]) {
        const int src = g_src[row];
        const float4* s = (const float4*)(x + (size_t)(batch * Ln + src) * Dn);
        dst[tid] = s[tid];
    } else {
        dst[tid] = make_float4(0.f, 0.f, 0.f, 0.f);
    }
}

__global__ void finalize_kernel(float* __restrict__ o_loss)
{
    double sb = 0.0, sp = 0.0;
    for (int i = 0; i < Bn; i++) { sb += (double)g_len[i]; sp += g_sumP[i]; }
    const double F = sb / (double)BLn;
    const double G = sp / (double)BLn;
    const double N = 6.0;
    o_loss[0] = (float)(N / (N - 1.0) * ((N - 1.0) * F * G + (1.0 - F) * (1.0 - G)));
}

// ---------------------------------------------------------------------------
// Launch. Output layout (f32): x_down | P_down | b | p | lengths | ratio_loss
// ---------------------------------------------------------------------------
extern "C" void kernel_launch(void* const* d_in, const int* in_sizes, int n_in,
                              void* d_out, int out_size)
{
    const float* x  = (const float*)d_in[0];
    const float* Wq = (const float*)d_in[1];
    const float* Wk = (const float*)d_in[2];

    float* out    = (float*)d_out;
    float* o_xd   = out;
    float* o_P    = out + (size_t)BLn * Dn;
    float* o_b    = o_P + BLn;
    float* o_p    = o_b + BLn;
    float* o_len  = o_p + BLn;
    float* o_loss = o_len + Bn;

    cudaFuncSetAttribute(hgemm_kernel,
                         cudaFuncAttributeMaxDynamicSharedMemorySize, GEMM_SMEM);

    split_w_kernel<<<(Dn * Dn / 4 + 255) / 256, 256>>>(Wq, 0, Dn * Dn / 4);
    split_w_kernel<<<(Dn * Dn / 4 + 255) / 256, 256>>>(Wk, 1, Dn * Dn / 4);
    split_x_kernel<<<(BLn * Dn / 4 + 255) / 256, 256>>>(x, BLn * Dn / 4);

    hgemm_kernel<<<dim3(8, 256, 2), 256, GEMM_SMEM>>>();

    props_kernel<<<BLn, 128>>>(o_p, o_b);
    fixup_kernel<<<64, 256>>>(x, Wq, Wk, o_b);
    scan_kernel<<<Bn, 256>>>(o_p, o_b, o_P, o_len);
    gather_kernel<<<BLn, 256>>>(x, o_xd);
    finalize_kernel<<<1, 1>>>(o_loss);
}

// round 8
// speedup vs baseline: 1.6815x; 1.5688x over previous
#include <cuda_runtime.h>
#include <cuda_bf16.h>
#include <stdint.h>
#include <math.h>

// Problem shape (fixed)
#define Bn 4
#define Ln 8192
#define Dn 1024
#define BLn (Bn * Ln)   // 32768 tokens
#define MAXFIX 64

// ---------------------------------------------------------------------------
// Scratch (device globals)
// ---------------------------------------------------------------------------
__device__ float  g_q[(size_t)BLn * Dn];                 // 128 MB
__device__ float  g_k[(size_t)BLn * Dn];                 // 128 MB
__device__ __nv_bfloat16 g_xh[2][(size_t)BLn * Dn];     // 128 MB (x splits)
__device__ __nv_bfloat16 g_wh[2][2][(size_t)Dn * Dn];   // 8 MB   (Wq/Wk splits)
__device__ int    g_src[BLn];
__device__ int    g_len[Bn];
__device__ double g_sumP[Bn];
__device__ int    g_nfix;
__device__ int    g_fix[MAXFIX];
__device__ double g_fixacc[3][MAXFIX];

// ---------------------------------------------------------------------------
// helpers
// ---------------------------------------------------------------------------
__device__ __forceinline__ uint32_t cvta_shared_u32(const void* p) {
    uint32_t r;
    asm("{ .reg .u64 t; cvta.to.shared.u64 t, %1; cvt.u32.u64 %0, t; }"
        : "=r"(r) : "l"(p));
    return r;
}
#define LDMATRIX_X4(r0, r1, r2, r3, addr)                                  \
    asm volatile("ldmatrix.sync.aligned.m8n8.x4.shared.b16 {%0,%1,%2,%3}, [%4];" \
                 : "=r"(r0), "=r"(r1), "=r"(r2), "=r"(r3) : "r"(addr))
#define MMA16816(c0, c1, c2, c3, a0, a1, a2, a3, b0, b1)                   \
    asm volatile("mma.sync.aligned.m16n8k16.row.col.f32.bf16.bf16.f32 "    \
                 "{%0,%1,%2,%3}, {%4,%5,%6,%7}, {%8,%9}, {%0,%1,%2,%3};"   \
                 : "+f"(c0), "+f"(c1), "+f"(c2), "+f"(c3)                  \
                 : "r"(a0), "r"(a1), "r"(a2), "r"(a3), "r"(b0), "r"(b1))
#define CP_ASYNC16(saddr, gaddr)                                           \
    asm volatile("cp.async.cg.shared.global [%0], [%1], 16;"               \
                 :: "r"(saddr), "l"(gaddr))

// ---------------------------------------------------------------------------
// Splits: f32 -> 2 exact bf16 splits (h0 + h1; dropped tail ~2^-17 rel).
// ---------------------------------------------------------------------------
__global__ void split_x_kernel(const float* __restrict__ src, int n4)
{
    int i = blockIdx.x * blockDim.x + threadIdx.x;
    if (i >= n4) return;
    const float4 v = ((const float4*)src)[i];
    float a[4] = {v.x, v.y, v.z, v.w};
    unsigned short s0[4], s1[4];
    #pragma unroll
    for (int c = 0; c < 4; c++) {
        const __nv_bfloat16 h0 = __float2bfloat16_rn(a[c]);
        const float r1 = a[c] - __bfloat162float(h0);
        const __nv_bfloat16 h1 = __float2bfloat16_rn(r1);
        s0[c] = __bfloat16_as_ushort(h0);
        s1[c] = __bfloat16_as_ushort(h1);
    }
    uint2 u0, u1;
    u0.x = (uint32_t)s0[0] | ((uint32_t)s0[1] << 16);
    u0.y = (uint32_t)s0[2] | ((uint32_t)s0[3] << 16);
    u1.x = (uint32_t)s1[0] | ((uint32_t)s1[1] << 16);
    u1.y = (uint32_t)s1[2] | ((uint32_t)s1[3] << 16);
    ((uint2*)&g_xh[0][0])[i] = u0;
    ((uint2*)&g_xh[1][0])[i] = u1;
}

__global__ void split_w_kernel(const float* __restrict__ src, int which, int n4)
{
    int i = blockIdx.x * blockDim.x + threadIdx.x;
    if (i >= n4) return;
    if (i == 0 && which == 0) g_nfix = 0;   // reset fixup list each replay
    const float4 v = ((const float4*)src)[i];
    float a[4] = {v.x, v.y, v.z, v.w};
    unsigned short s0[4], s1[4];
    #pragma unroll
    for (int c = 0; c < 4; c++) {
        const __nv_bfloat16 h0 = __float2bfloat16_rn(a[c]);
        const float r1 = a[c] - __bfloat162float(h0);
        const __nv_bfloat16 h1 = __float2bfloat16_rn(r1);
        s0[c] = __bfloat16_as_ushort(h0);
        s1[c] = __bfloat16_as_ushort(h1);
    }
    uint2 u0, u1;
    u0.x = (uint32_t)s0[0] | ((uint32_t)s0[1] << 16);
    u0.y = (uint32_t)s0[2] | ((uint32_t)s0[3] << 16);
    u1.x = (uint32_t)s1[0] | ((uint32_t)s1[1] << 16);
    u1.y = (uint32_t)s1[2] | ((uint32_t)s1[3] << 16);
    ((uint2*)&g_wh[which][0][0])[i] = u0;
    ((uint2*)&g_wh[which][1][0])[i] = u1;
}

// ---------------------------------------------------------------------------
// HMMA bf16x2 GEMM: C = X * W^T via 3 bf16 products (00, 01, 10).
// Tile 128x128, BK=32, 256 threads (8 warps as 2x4), warp tile 64x32.
// 2 smem buffers, loads issued then wait_group 1, 2 syncs/chunk.
// grid = (8 n-tiles, 256 m-tiles, 2 gemms).
// ---------------------------------------------------------------------------
#define SPLIT_BYTES 8192                   // 128 rows * 64 B
#define SIDE_BYTES  (2 * SPLIT_BYTES)      // 16384
#define BUF_BYTES   (2 * SIDE_BYTES)       // 32768 (A side + B side)
#define GEMM_SMEM   (2 * BUF_BYTES)        // 65536

// swizzled byte offset of 16B unit u (0..3) in row r (64B rows)
__device__ __forceinline__ uint32_t sw_off(int r, int u) {
    return (uint32_t)(64 * r + 16 * ((u + (r >> 1)) & 3));
}

__global__ __launch_bounds__(256, 2)
void hgemm_kernel()
{
    extern __shared__ char smem[];
    const uint32_t sbase = cvta_shared_u32(smem);

    const int tid  = threadIdx.x;
    const int wid  = tid >> 5;
    const int lane = tid & 31;
    const int wm   = wid & 1;          // 0..1 : 64-row half
    const int wn   = wid >> 1;         // 0..3 : 32-col quarter
    const int tn = blockIdx.x, tm = blockIdx.y, gz = blockIdx.z;

    const int j    = lane >> 3;        // ldmatrix matrix id 0..3
    const int rlow = lane & 7;

    int rA[4], rB[2];
    #pragma unroll
    for (int mt = 0; mt < 4; mt++)
        rA[mt] = wm * 64 + mt * 16 + (j & 1) * 8 + rlow;
    #pragma unroll
    for (int g = 0; g < 2; g++)
        rB[g] = wn * 32 + g * 16 + (j & 1) * 8 + rlow;
    const int jhi = j >> 1;

    float acc[4][4][4];
    #pragma unroll
    for (int mt = 0; mt < 4; mt++)
        #pragma unroll
        for (int nt = 0; nt < 4; nt++)
            #pragma unroll
            for (int e = 0; e < 4; e++) acc[mt][nt][e] = 0.0f;

    const char* xbase = (const char*)&g_xh[0][0] + (size_t)(tm * 128) * (Dn * 2);
    const char* wbase = (const char*)&g_wh[gz][0][0] + (size_t)(tn * 128) * (Dn * 2);
    const size_t XSPL = (size_t)BLn * Dn * 2;
    const size_t WSPL = (size_t)Dn * Dn * 2;

    // loader: 8 x 16B units per thread per chunk (2048 units total)
    int l_side[8], l_s[8], l_r[8], l_u[8];
    #pragma unroll
    for (int i = 0; i < 8; i++) {
        const int v    = tid + i * 256;
        const int side = v >= 1024;
        const int w    = v & 1023;
        l_side[i] = side;
        l_s[i]    = w >> 9;
        l_r[i]    = (w >> 2) & 127;
        l_u[i]    = w & 3;
    }

    #define LOAD_CHUNK(buf, c)                                                  \
    do {                                                                        \
        const uint32_t bb = sbase + (buf) * BUF_BYTES;                          \
        _Pragma("unroll")                                                       \
        for (int i = 0; i < 8; i++) {                                           \
            const uint32_t sa = bb + l_side[i] * SIDE_BYTES +                   \
                                l_s[i] * SPLIT_BYTES + sw_off(l_r[i], l_u[i]);  \
            const char* ga = (l_side[i] ? wbase + l_s[i] * WSPL                 \
                                        : xbase + l_s[i] * XSPL) +              \
                             (size_t)l_r[i] * (Dn * 2) + (c) * 64 + l_u[i] * 16;\
            CP_ASYNC16(sa, ga);                                                 \
        }                                                                       \
        asm volatile("cp.async.commit_group;");                                 \
    } while (0)

    const int NCH = Dn / 32;   // 32 chunks
    LOAD_CHUNK(0, 0);

    for (int c = 0; c < NCH; c++) {
        const int buf = c & 1;
        if (c + 1 < NCH) {
            LOAD_CHUNK(buf ^ 1, c + 1);
            asm volatile("cp.async.wait_group 1;");
        } else {
            asm volatile("cp.async.wait_group 0;");
        }
        __syncthreads();

        const uint32_t aB = sbase + buf * BUF_BYTES;
        const uint32_t bB = aB + SIDE_BYTES;

        #pragma unroll
        for (int ks = 0; ks < 2; ks++) {
            uint32_t bfr[2][4][2];
            #pragma unroll
            for (int s = 0; s < 2; s++) {
                #pragma unroll
                for (int g = 0; g < 2; g++) {
                    uint32_t r0, r1, r2, r3;
                    const uint32_t addr = bB + s * SPLIT_BYTES + 64 * rB[g] +
                        16 * (((2 * ks + jhi) + (rB[g] >> 1)) & 3);
                    LDMATRIX_X4(r0, r1, r2, r3, addr);
                    bfr[s][2 * g + 0][0] = r0; bfr[s][2 * g + 0][1] = r2;
                    bfr[s][2 * g + 1][0] = r1; bfr[s][2 * g + 1][1] = r3;
                }
            }
            #pragma unroll
            for (int pa = 0; pa < 2; pa++) {
                uint32_t afr[4][4];
                #pragma unroll
                for (int mt = 0; mt < 4; mt++) {
                    const uint32_t addr = aB + pa * SPLIT_BYTES + 64 * rA[mt] +
                        16 * (((2 * ks + jhi) + (rA[mt] >> 1)) & 3);
                    LDMATRIX_X4(afr[mt][0], afr[mt][1], afr[mt][2], afr[mt][3], addr);
                }
                const int npb = (pa == 0) ? 2 : 1;   // products 00, 01, 10
                for (int pb = 0; pb < npb; pb++) {
                    #pragma unroll
                    for (int mt = 0; mt < 4; mt++)
                        #pragma unroll
                        for (int nt = 0; nt < 4; nt++)
                            MMA16816(acc[mt][nt][0], acc[mt][nt][1],
                                     acc[mt][nt][2], acc[mt][nt][3],
                                     afr[mt][0], afr[mt][1], afr[mt][2], afr[mt][3],
                                     bfr[pb][nt][0], bfr[pb][nt][1]);
                }
            }
        }
        __syncthreads();
    }

    // epilogue
    float* C = (gz == 0) ? g_q : g_k;
    const int rowb = tm * 128 + wm * 64 + (lane >> 2);
    const int colb = tn * 128 + wn * 32 + 2 * (lane & 3);
    #pragma unroll
    for (int mt = 0; mt < 4; mt++) {
        #pragma unroll
        for (int nt = 0; nt < 4; nt++) {
            const size_t r0 = (size_t)(rowb + mt * 16) * Dn + colb + nt * 8;
            *(float2*)&C[r0]          = make_float2(acc[mt][nt][0], acc[mt][nt][1]);
            *(float2*)&C[r0 + 8 * Dn] = make_float2(acc[mt][nt][2], acc[mt][nt][3]);
        }
    }
    #undef LOAD_CHUNK
}

// ---------------------------------------------------------------------------
// Per-token props: p, b (fp64 reductions); flag borderline |cos| for fixup.
// ---------------------------------------------------------------------------
__global__ void props_kernel(float* __restrict__ out_p, float* __restrict__ out_b)
{
    const int t   = blockIdx.x;
    const int l   = t & (Ln - 1);
    const int tid = threadIdx.x;

    if (l == 0) {
        if (tid == 0) { out_p[t] = 1.0f; out_b[t] = 1.0f; }
        return;
    }
    const float4* qr = (const float4*)(g_q + (size_t)t * Dn);
    const float4* kr = (const float4*)(g_k + (size_t)(t - 1) * Dn);

    double sq = 0.0, sk = 0.0, sp = 0.0;
    #pragma unroll
    for (int it = 0; it < 2; it++) {
        const float4 qv = qr[tid + it * 128];
        const float4 kv = kr[tid + it * 128];
        sq += (double)qv.x * qv.x + (double)qv.y * qv.y +
              (double)qv.z * qv.z + (double)qv.w * qv.w;
        sk += (double)kv.x * kv.x + (double)kv.y * kv.y +
              (double)kv.z * kv.z + (double)kv.w * kv.w;
        sp += (double)qv.x * kv.x + (double)qv.y * kv.y +
              (double)qv.z * kv.z + (double)qv.w * kv.w;
    }
    #pragma unroll
    for (int o = 16; o > 0; o >>= 1) {
        sq += __shfl_down_sync(0xffffffffu, sq, o);
        sk += __shfl_down_sync(0xffffffffu, sk, o);
        sp += __shfl_down_sync(0xffffffffu, sp, o);
    }
    __shared__ double sh[3][4];
    const int wid = tid >> 5, lane = tid & 31;
    if (lane == 0) { sh[0][wid] = sq; sh[1][wid] = sk; sh[2][wid] = sp; }
    __syncthreads();
    if (tid == 0) {
        const double SQ = sh[0][0] + sh[0][1] + sh[0][2] + sh[0][3];
        const double SK = sh[1][0] + sh[1][1] + sh[1][2] + sh[1][3];
        const double SP = sh[2][0] + sh[2][1] + sh[2][2] + sh[2][3];
        const float nq = fmaxf(sqrtf((float)SQ), 1e-12f);
        const float nk = fmaxf(sqrtf((float)SK), 1e-12f);
        const float cs = (float)SP / (nq * nk);
        const float pv = 0.5f * (1.0f - cs);
        out_p[t] = pv;
        out_b[t] = (pv >= 0.5f) ? 1.0f : 0.0f;
        if (fabsf(cs) < 1e-5f) {
            const int ix = atomicAdd(&g_nfix, 1);
            if (ix < MAXFIX) {
                g_fix[ix] = t;
                g_fixacc[0][ix] = 0.0;
                g_fixacc[1][ix] = 0.0;
                g_fixacc[2][ix] = 0.0;
            }
        }
    }
}

// ---------------------------------------------------------------------------
// Fixup stage 1: exact partial sums for flagged tokens, coalesced reads.
// grid = (8 e-slices, MAXFIX token slots), 256 threads.
// Warp handles E-rows; lanes stride the D dimension (float4, coalesced).
// ---------------------------------------------------------------------------
__global__ void fixup_partial_kernel(const float* __restrict__ x,
                                     const float* __restrict__ Wq,
                                     const float* __restrict__ Wk)
{
    const int nf = (g_nfix < MAXFIX) ? g_nfix : MAXFIX;
    const int it = blockIdx.y;
    if (it >= nf) return;
    const int t  = g_fix[it];
    const int sl = blockIdx.x;              // e-slice: 128 rows
    const int tid = threadIdx.x;
    const int lane = tid & 31, wrp = tid >> 5;

    __shared__ float xs[Dn], xp[Dn];
    for (int d = tid; d < Dn; d += 256) {
        xs[d] = x[(size_t)t * Dn + d];
        xp[d] = x[(size_t)(t - 1) * Dn + d];
    }
    __syncthreads();

    double sq = 0.0, sk = 0.0, sp = 0.0;
    #pragma unroll 1
    for (int i = 0; i < 16; i++) {
        const int e = sl * 128 + wrp * 16 + i;
        const float4* wq = (const float4*)(Wq + (size_t)e * Dn);
        const float4* wk = (const float4*)(Wk + (size_t)e * Dn);
        double qd = 0.0, kd = 0.0;
        #pragma unroll
        for (int jj = 0; jj < 8; jj++) {
            const int d4 = lane + jj * 32;
            const float4 w4 = wq[d4];
            const float4 v4 = wk[d4];
            const float4 a4 = *(const float4*)&xs[d4 * 4];
            const float4 b4 = *(const float4*)&xp[d4 * 4];
            float qp = a4.x * w4.x;
            qp = fmaf(a4.y, w4.y, qp); qp = fmaf(a4.z, w4.z, qp); qp = fmaf(a4.w, w4.w, qp);
            float kp = b4.x * v4.x;
            kp = fmaf(b4.y, v4.y, kp); kp = fmaf(b4.z, v4.z, kp); kp = fmaf(b4.w, v4.w, kp);
            qd += (double)qp;
            kd += (double)kp;
        }
        #pragma unroll
        for (int o = 16; o > 0; o >>= 1) {
            qd += __shfl_down_sync(0xffffffffu, qd, o);
            kd += __shfl_down_sync(0xffffffffu, kd, o);
        }
        if (lane == 0) { sq += qd * qd; sk += kd * kd; sp += qd * kd; }
    }
    if (lane == 0) {
        atomicAdd(&g_fixacc[0][it], sq);
        atomicAdd(&g_fixacc[1][it], sk);
        atomicAdd(&g_fixacc[2][it], sp);
    }
}

// Fixup stage 2: decide b from the exact sums.
__global__ void fixup_apply_kernel(float* __restrict__ out_b)
{
    const int i = threadIdx.x;
    const int nf = (g_nfix < MAXFIX) ? g_nfix : MAXFIX;
    if (i < nf) {
        const double cs = g_fixacc[2][i] / sqrt(g_fixacc[0][i] * g_fixacc[1][i]);
        out_b[g_fix[i]] = (cs <= 0.0) ? 1.0f : 0.0f;
    }
}

// ---------------------------------------------------------------------------
// Per-batch scan of b
// ---------------------------------------------------------------------------
__global__ void scan_kernel(const float* __restrict__ p_arr,
                            const float* __restrict__ b_arr,
                            float* __restrict__ P_down,
                            float* __restrict__ out_len)
{
    const int batch = blockIdx.x;
    const int tid   = threadIdx.x;
    const float* bb = b_arr + batch * Ln;
    const float* pp = p_arr + batch * Ln;
    const int base  = tid * 32;

    int    cnt  = 0;
    double sump = 0.0;
    #pragma unroll 8
    for (int jj = 0; jj < 32; jj++) {
        const float bv = bb[base + jj];
        cnt  += (bv > 0.5f) ? 1 : 0;
        sump += (double)pp[base + jj];
    }
    const int lane = tid & 31, wid = tid >> 5;
    int v = cnt;
    #pragma unroll
    for (int o = 1; o < 32; o <<= 1) {
        const int n = __shfl_up_sync(0xffffffffu, v, o);
        if (lane >= o) v += n;
    }
    __shared__ int wsum[8], woff[8], stotal;
    if (lane == 31) wsum[wid] = v;
    __syncthreads();
    if (tid == 0) {
        int s = 0;
        for (int w = 0; w < 8; w++) { woff[w] = s; s += wsum[w]; }
        stotal = s;
    }
    __syncthreads();

    int slot = woff[wid] + v - cnt;
    const int total = stotal;

    for (int jj = 0; jj < 32; jj++) {
        const float bv = bb[base + jj];
        if (bv > 0.5f) {
            const int l = base + jj;
            g_src[batch * Ln + slot]  = l;
            P_down[batch * Ln + slot] = pp[l];
            slot++;
        }
    }
    for (int s = total + tid; s < Ln; s += 256)
        P_down[batch * Ln + s] = 0.0f;

    #pragma unroll
    for (int o = 16; o > 0; o >>= 1)
        sump += __shfl_down_sync(0xffffffffu, sump, o);
    __shared__ double psh[8];
    if (lane == 0) psh[wid] = sump;
    __syncthreads();
    if (tid == 0) {
        double s = 0.0;
        for (int w = 0; w < 8; w++) s += psh[w];
        g_sumP[batch]  = s;
        g_len[batch]   = total;
        out_len[batch] = (float)total;
    }
}

// ---------------------------------------------------------------------------
// Gather x_down
// ---------------------------------------------------------------------------
__global__ void gather_kernel(const float* __restrict__ x, float* __restrict__ x_down)
{
    const int row   = blockIdx.x;
    const int batch = row >> 13;
    const int jj    = row & (Ln - 1);
    const int tid   = threadIdx.x;

    float4* dst = (float4*)(x_down + (size_t)row * Dn);
    if (jj < g_len[batch]) {
        const int src = g_src[row];
        const float4* s = (const float4*)(x + (size_t)(batch * Ln + src) * Dn);
        dst[tid] = s[tid];
    } else {
        dst[tid] = make_float4(0.f, 0.f, 0.f, 0.f);
    }
}

__global__ void finalize_kernel(float* __restrict__ o_loss)
{
    double sb = 0.0, sp = 0.0;
    for (int i = 0; i < Bn; i++) { sb += (double)g_len[i]; sp += g_sumP[i]; }
    const double F = sb / (double)BLn;
    const double G = sp / (double)BLn;
    const double N = 6.0;
    o_loss[0] = (float)(N / (N - 1.0) * ((N - 1.0) * F * G + (1.0 - F) * (1.0 - G)));
}

// ---------------------------------------------------------------------------
// Launch. Output layout (f32): x_down | P_down | b | p | lengths | ratio_loss
// ---------------------------------------------------------------------------
extern "C" void kernel_launch(void* const* d_in, const int* in_sizes, int n_in,
                              void* d_out, int out_size)
{
    const float* x  = (const float*)d_in[0];
    const float* Wq = (const float*)d_in[1];
    const float* Wk = (const float*)d_in[2];

    float* out    = (float*)d_out;
    float* o_xd   = out;
    float* o_P    = out + (size_t)BLn * Dn;
    float* o_b    = o_P + BLn;
    float* o_p    = o_b + BLn;
    float* o_len  = o_p + BLn;
    float* o_loss = o_len + Bn;

    cudaFuncSetAttribute(hgemm_kernel,
                         cudaFuncAttributeMaxDynamicSharedMemorySize, GEMM_SMEM);

    split_w_kernel<<<(Dn * Dn / 4 + 255) / 256, 256>>>(Wq, 0, Dn * Dn / 4);
    split_w_kernel<<<(Dn * Dn / 4 + 255) / 256, 256>>>(Wk, 1, Dn * Dn / 4);
    split_x_kernel<<<(BLn * Dn / 4 + 255) / 256, 256>>>(x, BLn * Dn / 4);

    hgemm_kernel<<<dim3(8, 256, 2), 256, GEMM_SMEM>>>();

    props_kernel<<<BLn, 128>>>(o_p, o_b);
    fixup_partial_kernel<<<dim3(8, MAXFIX), 256>>>(x, Wq, Wk);
    fixup_apply_kernel<<<1, MAXFIX>>>(o_b);
    scan_kernel<<<Bn, 256>>>(o_p, o_b, o_P, o_len);
    gather_kernel<<<BLn, 256>>>(x, o_xd);
    finalize_kernel<<<1, 1>>>(o_loss);
}

// round 9
// speedup vs baseline: 2.2982x; 1.3667x over previous
#include <cuda_runtime.h>
#include <cuda_fp16.h>
#include <stdint.h>
#include <math.h>

// Problem shape (fixed)
#define Bn 4
#define Ln 8192
#define Dn 1024
#define BLn (Bn * Ln)   // 32768 tokens
#define MAXFIX 512

// ---------------------------------------------------------------------------
// Scratch (device globals)
// ---------------------------------------------------------------------------
__device__ float  g_q[(size_t)BLn * Dn];            // 128 MB (holds 32*q)
__device__ float  g_k[(size_t)BLn * Dn];            // 128 MB (holds 32*k)
__device__ __half g_xh[(size_t)BLn * Dn];           // 64 MB  (x as fp16)
__device__ __half g_wh[2][(size_t)Dn * Dn];         // 4 MB   (32*Wq, 32*Wk as fp16)
__device__ int    g_src[BLn];
__device__ int    g_len[Bn];
__device__ double g_sumP[Bn];
__device__ int    g_nfix;
__device__ int    g_fix[MAXFIX];
__device__ double g_fixacc[3][MAXFIX];

// ---------------------------------------------------------------------------
// helpers
// ---------------------------------------------------------------------------
__device__ __forceinline__ uint32_t cvta_shared_u32(const void* p) {
    uint32_t r;
    asm("{ .reg .u64 t; cvta.to.shared.u64 t, %1; cvt.u32.u64 %0, t; }"
        : "=r"(r) : "l"(p));
    return r;
}
#define LDMATRIX_X4(r0, r1, r2, r3, addr)                                  \
    asm volatile("ldmatrix.sync.aligned.m8n8.x4.shared.b16 {%0,%1,%2,%3}, [%4];" \
                 : "=r"(r0), "=r"(r1), "=r"(r2), "=r"(r3) : "r"(addr))
#define MMA16816(c0, c1, c2, c3, a0, a1, a2, a3, b0, b1)                   \
    asm volatile("mma.sync.aligned.m16n8k16.row.col.f32.f16.f16.f32 "      \
                 "{%0,%1,%2,%3}, {%4,%5,%6,%7}, {%8,%9}, {%0,%1,%2,%3};"   \
                 : "+f"(c0), "+f"(c1), "+f"(c2), "+f"(c3)                  \
                 : "r"(a0), "r"(a1), "r"(a2), "r"(a3), "r"(b0), "r"(b1))
#define CP_ASYNC16(saddr, gaddr)                                           \
    asm volatile("cp.async.cg.shared.global [%0], [%1], 16;"               \
                 :: "r"(saddr), "l"(gaddr))

// ---------------------------------------------------------------------------
// Converts: x -> fp16; W -> fp16 scaled by 32 (exact pow2; cos is
// scale-invariant, keeps W entries ~N(0,1) in fp16's sweet spot).
// ---------------------------------------------------------------------------
__global__ void conv_x_kernel(const float* __restrict__ src, int n4)
{
    int i = blockIdx.x * blockDim.x + threadIdx.x;
    if (i >= n4) return;
    const float4 v = ((const float4*)src)[i];
    const __half2 h0 = __floats2half2_rn(v.x, v.y);
    const __half2 h1 = __floats2half2_rn(v.z, v.w);
    uint2 u;
    u.x = *(const uint32_t*)&h0;
    u.y = *(const uint32_t*)&h1;
    ((uint2*)&g_xh[0])[i] = u;
}

__global__ void conv_w_kernel(const float* __restrict__ src, int which, int n4)
{
    int i = blockIdx.x * blockDim.x + threadIdx.x;
    if (i >= n4) return;
    if (i == 0 && which == 0) g_nfix = 0;   // reset fixup list each replay
    const float4 v = ((const float4*)src)[i];
    const __half2 h0 = __floats2half2_rn(32.0f * v.x, 32.0f * v.y);
    const __half2 h1 = __floats2half2_rn(32.0f * v.z, 32.0f * v.w);
    uint2 u;
    u.x = *(const uint32_t*)&h0;
    u.y = *(const uint32_t*)&h1;
    ((uint2*)&g_wh[which][0])[i] = u;
}

// ---------------------------------------------------------------------------
// HMMA fp16 GEMM (single product): C = X * W^T.
// Tile 128x128, BK=32, 256 threads (8 warps as 2x4), warp tile 64x32.
// 2 smem buffers, loads issued then wait_group 1, 2 syncs/chunk.
// grid = (8 n-tiles, 256 m-tiles, 2 gemms).
// ---------------------------------------------------------------------------
#define SIDE_BYTES  8192                   // 128 rows * 64 B
#define BUF_BYTES   (2 * SIDE_BYTES)       // 16384 (A side + B side)
#define GEMM_SMEM   (2 * BUF_BYTES)        // 32768

// swizzled byte offset of 16B unit u (0..3) in row r (64B rows)
__device__ __forceinline__ uint32_t sw_off(int r, int u) {
    return (uint32_t)(64 * r + 16 * ((u + (r >> 1)) & 3));
}

__global__ __launch_bounds__(256, 2)
void hgemm_kernel()
{
    extern __shared__ char smem[];
    const uint32_t sbase = cvta_shared_u32(smem);

    const int tid  = threadIdx.x;
    const int wid  = tid >> 5;
    const int lane = tid & 31;
    const int wm   = wid & 1;          // 0..1 : 64-row half
    const int wn   = wid >> 1;         // 0..3 : 32-col quarter
    const int tn = blockIdx.x, tm = blockIdx.y, gz = blockIdx.z;

    const int j    = lane >> 3;        // ldmatrix matrix id 0..3
    const int rlow = lane & 7;

    int rA[4], rB[2];
    #pragma unroll
    for (int mt = 0; mt < 4; mt++)
        rA[mt] = wm * 64 + mt * 16 + (j & 1) * 8 + rlow;
    #pragma unroll
    for (int g = 0; g < 2; g++)
        rB[g] = wn * 32 + g * 16 + (j & 1) * 8 + rlow;
    const int jhi = j >> 1;

    float acc[4][4][4];
    #pragma unroll
    for (int mt = 0; mt < 4; mt++)
        #pragma unroll
        for (int nt = 0; nt < 4; nt++)
            #pragma unroll
            for (int e = 0; e < 4; e++) acc[mt][nt][e] = 0.0f;

    const char* xbase = (const char*)&g_xh[0] + (size_t)(tm * 128) * (Dn * 2);
    const char* wbase = (const char*)&g_wh[gz][0] + (size_t)(tn * 128) * (Dn * 2);

    // loader: 4 x 16B units per thread per chunk (1024 units total)
    int l_side[4], l_r[4], l_u[4];
    #pragma unroll
    for (int i = 0; i < 4; i++) {
        const int v    = tid + i * 256;
        const int side = v >= 512;
        const int w    = v & 511;
        l_side[i] = side;
        l_r[i]    = w >> 2;
        l_u[i]    = w & 3;
    }

    #define LOAD_CHUNK(buf, c)                                                  \
    do {                                                                        \
        const uint32_t bb = sbase + (buf) * BUF_BYTES;                          \
        _Pragma("unroll")                                                       \
        for (int i = 0; i < 4; i++) {                                           \
            const uint32_t sa = bb + l_side[i] * SIDE_BYTES +                   \
                                sw_off(l_r[i], l_u[i]);                         \
            const char* ga = (l_side[i] ? wbase : xbase) +                      \
                             (size_t)l_r[i] * (Dn * 2) + (c) * 64 + l_u[i] * 16;\
            CP_ASYNC16(sa, ga);                                                 \
        }                                                                       \
        asm volatile("cp.async.commit_group;");                                 \
    } while (0)

    const int NCH = Dn / 32;   // 32 chunks
    LOAD_CHUNK(0, 0);

    for (int c = 0; c < NCH; c++) {
        const int buf = c & 1;
        if (c + 1 < NCH) {
            LOAD_CHUNK(buf ^ 1, c + 1);
            asm volatile("cp.async.wait_group 1;");
        } else {
            asm volatile("cp.async.wait_group 0;");
        }
        __syncthreads();

        const uint32_t aB = sbase + buf * BUF_BYTES;
        const uint32_t bB = aB + SIDE_BYTES;

        #pragma unroll
        for (int ks = 0; ks < 2; ks++) {
            uint32_t bfr[4][2];
            #pragma unroll
            for (int g = 0; g < 2; g++) {
                uint32_t r0, r1, r2, r3;
                const uint32_t addr = bB + 64 * rB[g] +
                    16 * (((2 * ks + jhi) + (rB[g] >> 1)) & 3);
                LDMATRIX_X4(r0, r1, r2, r3, addr);
                bfr[2 * g + 0][0] = r0; bfr[2 * g + 0][1] = r2;
                bfr[2 * g + 1][0] = r1; bfr[2 * g + 1][1] = r3;
            }
            uint32_t afr[4][4];
            #pragma unroll
            for (int mt = 0; mt < 4; mt++) {
                const uint32_t addr = aB + 64 * rA[mt] +
                    16 * (((2 * ks + jhi) + (rA[mt] >> 1)) & 3);
                LDMATRIX_X4(afr[mt][0], afr[mt][1], afr[mt][2], afr[mt][3], addr);
            }
            #pragma unroll
            for (int mt = 0; mt < 4; mt++)
                #pragma unroll
                for (int nt = 0; nt < 4; nt++)
                    MMA16816(acc[mt][nt][0], acc[mt][nt][1],
                             acc[mt][nt][2], acc[mt][nt][3],
                             afr[mt][0], afr[mt][1], afr[mt][2], afr[mt][3],
                             bfr[nt][0], bfr[nt][1]);
        }
        __syncthreads();
    }

    // epilogue (values are 32x the true q/k; cos is scale-invariant)
    float* C = (gz == 0) ? g_q : g_k;
    const int rowb = tm * 128 + wm * 64 + (lane >> 2);
    const int colb = tn * 128 + wn * 32 + 2 * (lane & 3);
    #pragma unroll
    for (int mt = 0; mt < 4; mt++) {
        #pragma unroll
        for (int nt = 0; nt < 4; nt++) {
            const size_t r0 = (size_t)(rowb + mt * 16) * Dn + colb + nt * 8;
            *(float2*)&C[r0]          = make_float2(acc[mt][nt][0], acc[mt][nt][1]);
            *(float2*)&C[r0 + 8 * Dn] = make_float2(acc[mt][nt][2], acc[mt][nt][3]);
        }
    }
    #undef LOAD_CHUNK
}

// ---------------------------------------------------------------------------
// Per-token props: p, b (fp64 reductions); flag borderline |cos| for fixup.
// fp16-GEMM cos error ~1.2e-5; threshold 1e-4 (~8 sigma).
// ---------------------------------------------------------------------------
__global__ void props_kernel(float* __restrict__ out_p, float* __restrict__ out_b)
{
    const int t   = blockIdx.x;
    const int l   = t & (Ln - 1);
    const int tid = threadIdx.x;

    if (l == 0) {
        if (tid == 0) { out_p[t] = 1.0f; out_b[t] = 1.0f; }
        return;
    }
    const float4* qr = (const float4*)(g_q + (size_t)t * Dn);
    const float4* kr = (const float4*)(g_k + (size_t)(t - 1) * Dn);

    double sq = 0.0, sk = 0.0, sp = 0.0;
    #pragma unroll
    for (int it = 0; it < 2; it++) {
        const float4 qv = qr[tid + it * 128];
        const float4 kv = kr[tid + it * 128];
        sq += (double)qv.x * qv.x + (double)qv.y * qv.y +
              (double)qv.z * qv.z + (double)qv.w * qv.w;
        sk += (double)kv.x * kv.x + (double)kv.y * kv.y +
              (double)kv.z * kv.z + (double)kv.w * kv.w;
        sp += (double)qv.x * kv.x + (double)qv.y * kv.y +
              (double)qv.z * kv.z + (double)qv.w * kv.w;
    }
    #pragma unroll
    for (int o = 16; o > 0; o >>= 1) {
        sq += __shfl_down_sync(0xffffffffu, sq, o);
        sk += __shfl_down_sync(0xffffffffu, sk, o);
        sp += __shfl_down_sync(0xffffffffu, sp, o);
    }
    __shared__ double sh[3][4];
    const int wid = tid >> 5, lane = tid & 31;
    if (lane == 0) { sh[0][wid] = sq; sh[1][wid] = sk; sh[2][wid] = sp; }
    __syncthreads();
    if (tid == 0) {
        const double SQ = sh[0][0] + sh[0][1] + sh[0][2] + sh[0][3];
        const double SK = sh[1][0] + sh[1][1] + sh[1][2] + sh[1][3];
        const double SP = sh[2][0] + sh[2][1] + sh[2][2] + sh[2][3];
        const float nq = fmaxf(sqrtf((float)SQ), 1e-12f);
        const float nk = fmaxf(sqrtf((float)SK), 1e-12f);
        const float cs = (float)SP / (nq * nk);
        const float pv = 0.5f * (1.0f - cs);
        out_p[t] = pv;
        out_b[t] = (pv >= 0.5f) ? 1.0f : 0.0f;
        if (fabsf(cs) < 1e-4f) {
            const int ix = atomicAdd(&g_nfix, 1);
            if (ix < MAXFIX) {
                g_fix[ix] = t;
                g_fixacc[0][ix] = 0.0;
                g_fixacc[1][ix] = 0.0;
                g_fixacc[2][ix] = 0.0;
            }
        }
    }
}

// ---------------------------------------------------------------------------
// Fixup stage 1: exact partial sums for flagged tokens, coalesced reads.
// grid = (8 e-slices, MAXFIX token slots), 256 threads.
// ---------------------------------------------------------------------------
__global__ void fixup_partial_kernel(const float* __restrict__ x,
                                     const float* __restrict__ Wq,
                                     const float* __restrict__ Wk)
{
    const int nf = (g_nfix < MAXFIX) ? g_nfix : MAXFIX;
    const int it = blockIdx.y;
    if (it >= nf) return;
    const int t  = g_fix[it];
    const int sl = blockIdx.x;              // e-slice: 128 rows
    const int tid = threadIdx.x;
    const int lane = tid & 31, wrp = tid >> 5;

    __shared__ float xs[Dn], xp[Dn];
    for (int d = tid; d < Dn; d += 256) {
        xs[d] = x[(size_t)t * Dn + d];
        xp[d] = x[(size_t)(t - 1) * Dn + d];
    }
    __syncthreads();

    double sq = 0.0, sk = 0.0, sp = 0.0;
    #pragma unroll 1
    for (int i = 0; i < 16; i++) {
        const int e = sl * 128 + wrp * 16 + i;
        const float4* wq = (const float4*)(Wq + (size_t)e * Dn);
        const float4* wk = (const float4*)(Wk + (size_t)e * Dn);
        double qd = 0.0, kd = 0.0;
        #pragma unroll
        for (int jj = 0; jj < 8; jj++) {
            const int d4 = lane + jj * 32;
            const float4 w4 = wq[d4];
            const float4 v4 = wk[d4];
            const float4 a4 = *(const float4*)&xs[d4 * 4];
            const float4 b4 = *(const float4*)&xp[d4 * 4];
            float qp = a4.x * w4.x;
            qp = fmaf(a4.y, w4.y, qp); qp = fmaf(a4.z, w4.z, qp); qp = fmaf(a4.w, w4.w, qp);
            float kp = b4.x * v4.x;
            kp = fmaf(b4.y, v4.y, kp); kp = fmaf(b4.z, v4.z, kp); kp = fmaf(b4.w, v4.w, kp);
            qd += (double)qp;
            kd += (double)kp;
        }
        #pragma unroll
        for (int o = 16; o > 0; o >>= 1) {
            qd += __shfl_down_sync(0xffffffffu, qd, o);
            kd += __shfl_down_sync(0xffffffffu, kd, o);
        }
        if (lane == 0) { sq += qd * qd; sk += kd * kd; sp += qd * kd; }
    }
    if (lane == 0) {
        atomicAdd(&g_fixacc[0][it], sq);
        atomicAdd(&g_fixacc[1][it], sk);
        atomicAdd(&g_fixacc[2][it], sp);
    }
}

// Fixup stage 2: decide b from the exact sums.
__global__ void fixup_apply_kernel(float* __restrict__ out_b)
{
    const int i = threadIdx.x;
    const int nf = (g_nfix < MAXFIX) ? g_nfix : MAXFIX;
    if (i < nf) {
        const double cs = g_fixacc[2][i] / sqrt(g_fixacc[0][i] * g_fixacc[1][i]);
        out_b[g_fix[i]] = (cs <= 0.0) ? 1.0f : 0.0f;
    }
}

// ---------------------------------------------------------------------------
// Per-batch scan of b
// ---------------------------------------------------------------------------
__global__ void scan_kernel(const float* __restrict__ p_arr,
                            const float* __restrict__ b_arr,
                            float* __restrict__ P_down,
                            float* __restrict__ out_len)
{
    const int batch = blockIdx.x;
    const int tid   = threadIdx.x;
    const float* bb = b_arr + batch * Ln;
    const float* pp = p_arr + batch * Ln;
    const int base  = tid * 32;

    int    cnt  = 0;
    double sump = 0.0;
    #pragma unroll 8
    for (int jj = 0; jj < 32; jj++) {
        const float bv = bb[base + jj];
        cnt  += (bv > 0.5f) ? 1 : 0;
        sump += (double)pp[base + jj];
    }
    const int lane = tid & 31, wid = tid >> 5;
    int v = cnt;
    #pragma unroll
    for (int o = 1; o < 32; o <<= 1) {
        const int n = __shfl_up_sync(0xffffffffu, v, o);
        if (lane >= o) v += n;
    }
    __shared__ int wsum[8], woff[8], stotal;
    if (lane == 31) wsum[wid] = v;
    __syncthreads();
    if (tid == 0) {
        int s = 0;
        for (int w = 0; w < 8; w++) { woff[w] = s; s += wsum[w]; }
        stotal = s;
    }
    __syncthreads();

    int slot = woff[wid] + v - cnt;
    const int total = stotal;

    for (int jj = 0; jj < 32; jj++) {
        const float bv = bb[base + jj];
        if (bv > 0.5f) {
            const int l = base + jj;
            g_src[batch * Ln + slot]  = l;
            P_down[batch * Ln + slot] = pp[l];
            slot++;
        }
    }
    for (int s = total + tid; s < Ln; s += 256)
        P_down[batch * Ln + s] = 0.0f;

    #pragma unroll
    for (int o = 16; o > 0; o >>= 1)
        sump += __shfl_down_sync(0xffffffffu, sump, o);
    __shared__ double psh[8];
    if (lane == 0) psh[wid] = sump;
    __syncthreads();
    if (tid == 0) {
        double s = 0.0;
        for (int w = 0; w < 8; w++) s += psh[w];
        g_sumP[batch]  = s;
        g_len[batch]   = total;
        out_len[batch] = (float)total;
    }
}

// ---------------------------------------------------------------------------
// Gather x_down
// ---------------------------------------------------------------------------
__global__ void gather_kernel(const float* __restrict__ x, float* __restrict__ x_down)
{
    const int row   = blockIdx.x;
    const int batch = row >> 13;
    const int jj    = row & (Ln - 1);
    const int tid   = threadIdx.x;

    float4* dst = (float4*)(x_down + (size_t)row * Dn);
    if (jj < g_len[batch]) {
        const int src = g_src[row];
        const float4* s = (const float4*)(x + (size_t)(batch * Ln + src) * Dn);
        dst[tid] = s[tid];
    } else {
        dst[tid] = make_float4(0.f, 0.f, 0.f, 0.f);
    }
}

__global__ void finalize_kernel(float* __restrict__ o_loss)
{
    double sb = 0.0, sp = 0.0;
    for (int i = 0; i < Bn; i++) { sb += (double)g_len[i]; sp += g_sumP[i]; }
    const double F = sb / (double)BLn;
    const double G = sp / (double)BLn;
    const double N = 6.0;
    o_loss[0] = (float)(N / (N - 1.0) * ((N - 1.0) * F * G + (1.0 - F) * (1.0 - G)));
}

// ---------------------------------------------------------------------------
// Launch. Output layout (f32): x_down | P_down | b | p | lengths | ratio_loss
// ---------------------------------------------------------------------------
extern "C" void kernel_launch(void* const* d_in, const int* in_sizes, int n_in,
                              void* d_out, int out_size)
{
    const float* x  = (const float*)d_in[0];
    const float* Wq = (const float*)d_in[1];
    const float* Wk = (const float*)d_in[2];

    float* out    = (float*)d_out;
    float* o_xd   = out;
    float* o_P    = out + (size_t)BLn * Dn;
    float* o_b    = o_P + BLn;
    float* o_p    = o_b + BLn;
    float* o_len  = o_p + BLn;
    float* o_loss = o_len + Bn;

    cudaFuncSetAttribute(hgemm_kernel,
                         cudaFuncAttributeMaxDynamicSharedMemorySize, GEMM_SMEM);

    conv_w_kernel<<<(Dn * Dn / 4 + 255) / 256, 256>>>(Wq, 0, Dn * Dn / 4);
    conv_w_kernel<<<(Dn * Dn / 4 + 255) / 256, 256>>>(Wk, 1, Dn * Dn / 4);
    conv_x_kernel<<<(BLn * Dn / 4 + 255) / 256, 256>>>(x, BLn * Dn / 4);

    hgemm_kernel<<<dim3(8, 256, 2), 256, GEMM_SMEM>>>();

    props_kernel<<<BLn, 128>>>(o_p, o_b);
    fixup_partial_kernel<<<dim3(8, MAXFIX), 256>>>(x, Wq, Wk);
    fixup_apply_kernel<<<1, MAXFIX>>>(o_b);
    scan_kernel<<<Bn, 256>>>(o_p, o_b, o_P, o_len);
    gather_kernel<<<BLn, 256>>>(x, o_xd);
    finalize_kernel<<<1, 1>>>(o_loss);
}

// round 10
// speedup vs baseline: 3.8615x; 1.6802x over previous
#include <cuda_runtime.h>
#include <cuda_fp16.h>
#include <stdint.h>
#include <math.h>

// Problem shape (fixed)
#define Bn 4
#define Ln 8192
#define Dn 1024
#define BLn (Bn * Ln)   // 32768 tokens
#define MAXFIX 512

// ---------------------------------------------------------------------------
// Scratch (device globals)
// ---------------------------------------------------------------------------
__device__ float  g_q[(size_t)BLn * Dn];            // 128 MB (holds 32*q)
__device__ float  g_k[(size_t)BLn * Dn];            // 128 MB (holds 32*k)
__device__ __half g_xh[(size_t)BLn * Dn];           // 64 MB  (x as fp16)
__device__ __half g_wh[2][(size_t)Dn * Dn];         // 4 MB   (32*Wq, 32*Wk as fp16)
__device__ int    g_src[BLn];
__device__ int    g_len[Bn];
__device__ double g_sumP[Bn];
__device__ int    g_nfix;
__device__ int    g_fix[MAXFIX];
__device__ double g_fixacc[3][MAXFIX];

// ---------------------------------------------------------------------------
// helpers
// ---------------------------------------------------------------------------
__device__ __forceinline__ uint32_t cvta_shared_u32(const void* p) {
    uint32_t r;
    asm("{ .reg .u64 t; cvta.to.shared.u64 t, %1; cvt.u32.u64 %0, t; }"
        : "=r"(r) : "l"(p));
    return r;
}
#define LDMATRIX_X4(r0, r1, r2, r3, addr)                                  \
    asm volatile("ldmatrix.sync.aligned.m8n8.x4.shared.b16 {%0,%1,%2,%3}, [%4];" \
                 : "=r"(r0), "=r"(r1), "=r"(r2), "=r"(r3) : "r"(addr))
#define MMA16816(c0, c1, c2, c3, a0, a1, a2, a3, b0, b1)                   \
    asm volatile("mma.sync.aligned.m16n8k16.row.col.f32.f16.f16.f32 "      \
                 "{%0,%1,%2,%3}, {%4,%5,%6,%7}, {%8,%9}, {%0,%1,%2,%3};"   \
                 : "+f"(c0), "+f"(c1), "+f"(c2), "+f"(c3)                  \
                 : "r"(a0), "r"(a1), "r"(a2), "r"(a3), "r"(b0), "r"(b1))
#define CP_ASYNC16(saddr, gaddr)                                           \
    asm volatile("cp.async.cg.shared.global [%0], [%1], 16;"               \
                 :: "r"(saddr), "l"(gaddr))

// ---------------------------------------------------------------------------
// Converts: x -> fp16; W -> fp16 scaled by 32 (exact pow2; cos is
// scale-invariant).
// ---------------------------------------------------------------------------
__global__ void conv_x_kernel(const float* __restrict__ src, int n4)
{
    int i = blockIdx.x * blockDim.x + threadIdx.x;
    if (i >= n4) return;
    const float4 v = ((const float4*)src)[i];
    const __half2 h0 = __floats2half2_rn(v.x, v.y);
    const __half2 h1 = __floats2half2_rn(v.z, v.w);
    uint2 u;
    u.x = *(const uint32_t*)&h0;
    u.y = *(const uint32_t*)&h1;
    ((uint2*)&g_xh[0])[i] = u;
}

__global__ void conv_w_kernel(const float* __restrict__ src, int which, int n4)
{
    int i = blockIdx.x * blockDim.x + threadIdx.x;
    if (i >= n4) return;
    if (i == 0 && which == 0) g_nfix = 0;   // reset fixup list each replay
    const float4 v = ((const float4*)src)[i];
    const __half2 h0 = __floats2half2_rn(32.0f * v.x, 32.0f * v.y);
    const __half2 h1 = __floats2half2_rn(32.0f * v.z, 32.0f * v.w);
    uint2 u;
    u.x = *(const uint32_t*)&h0;
    u.y = *(const uint32_t*)&h1;
    ((uint2*)&g_wh[which][0])[i] = u;
}

// ---------------------------------------------------------------------------
// HMMA fp16 GEMM (single product): C = X * W^T.
// Tile 128x128, BK=64 (128B rows, XOR swizzle), 256 threads (8 warps 2x4),
// warp tile 64x32.  2 smem buffers, loads issued then wait_group 1.
// grid = (8 n-tiles, 256 m-tiles, 2 gemms).
// ---------------------------------------------------------------------------
#define SIDE_BYTES  16384                  // 128 rows * 128 B
#define BUF_BYTES   (2 * SIDE_BYTES)       // 32768 (A side + B side)
#define GEMM_SMEM   (2 * BUF_BYTES)        // 65536

// swizzled byte offset of 16B unit u (0..7) in row r (128B rows)
__device__ __forceinline__ uint32_t sw_off(int r, int u) {
    return (uint32_t)(128 * r + 16 * (u ^ (r & 7)));
}

__global__ __launch_bounds__(256, 2)
void hgemm_kernel()
{
    extern __shared__ char smem[];
    const uint32_t sbase = cvta_shared_u32(smem);

    const int tid  = threadIdx.x;
    const int wid  = tid >> 5;
    const int lane = tid & 31;
    const int wm   = wid & 1;          // 0..1 : 64-row half
    const int wn   = wid >> 1;         // 0..3 : 32-col quarter
    const int tn = blockIdx.x, tm = blockIdx.y, gz = blockIdx.z;

    const int j    = lane >> 3;        // ldmatrix matrix id 0..3
    const int rlow = lane & 7;

    int rA[4], rB[2];
    #pragma unroll
    for (int mt = 0; mt < 4; mt++)
        rA[mt] = wm * 64 + mt * 16 + (j & 1) * 8 + rlow;
    #pragma unroll
    for (int g = 0; g < 2; g++)
        rB[g] = wn * 32 + g * 16 + (j & 1) * 8 + rlow;
    const int jhi = j >> 1;

    float acc[4][4][4];
    #pragma unroll
    for (int mt = 0; mt < 4; mt++)
        #pragma unroll
        for (int nt = 0; nt < 4; nt++)
            #pragma unroll
            for (int e = 0; e < 4; e++) acc[mt][nt][e] = 0.0f;

    const char* xbase = (const char*)&g_xh[0] + (size_t)(tm * 128) * (Dn * 2);
    const char* wbase = (const char*)&g_wh[gz][0] + (size_t)(tn * 128) * (Dn * 2);

    // loader: 8 x 16B units per thread per chunk (2048 units total)
    int l_side[8], l_r[8], l_u[8];
    #pragma unroll
    for (int i = 0; i < 8; i++) {
        const int v    = tid + i * 256;
        const int side = v >= 1024;
        const int w    = v & 1023;
        l_side[i] = side;
        l_r[i]    = w >> 3;
        l_u[i]    = w & 7;
    }

    #define LOAD_CHUNK(buf, c)                                                   \
    do {                                                                         \
        const uint32_t bb = sbase + (buf) * BUF_BYTES;                           \
        _Pragma("unroll")                                                        \
        for (int i = 0; i < 8; i++) {                                            \
            const uint32_t sa = bb + l_side[i] * SIDE_BYTES +                    \
                                sw_off(l_r[i], l_u[i]);                          \
            const char* ga = (l_side[i] ? wbase : xbase) +                       \
                             (size_t)l_r[i] * (Dn * 2) + (c) * 128 + l_u[i] * 16;\
            CP_ASYNC16(sa, ga);                                                  \
        }                                                                        \
        asm volatile("cp.async.commit_group;");                                  \
    } while (0)

    const int NCH = Dn / 64;   // 16 chunks
    LOAD_CHUNK(0, 0);

    for (int c = 0; c < NCH; c++) {
        const int buf = c & 1;
        if (c + 1 < NCH) {
            LOAD_CHUNK(buf ^ 1, c + 1);
            asm volatile("cp.async.wait_group 1;");
        } else {
            asm volatile("cp.async.wait_group 0;");
        }
        __syncthreads();

        const uint32_t aB = sbase + buf * BUF_BYTES;
        const uint32_t bB = aB + SIDE_BYTES;

        #pragma unroll
        for (int ks = 0; ks < 4; ks++) {
            uint32_t bfr[4][2];
            #pragma unroll
            for (int g = 0; g < 2; g++) {
                uint32_t r0, r1, r2, r3;
                const uint32_t addr = bB + 128 * rB[g] +
                    16 * ((2 * ks + jhi) ^ (rB[g] & 7));
                LDMATRIX_X4(r0, r1, r2, r3, addr);
                bfr[2 * g + 0][0] = r0; bfr[2 * g + 0][1] = r2;
                bfr[2 * g + 1][0] = r1; bfr[2 * g + 1][1] = r3;
            }
            uint32_t afr[4][4];
            #pragma unroll
            for (int mt = 0; mt < 4; mt++) {
                const uint32_t addr = aB + 128 * rA[mt] +
                    16 * ((2 * ks + jhi) ^ (rA[mt] & 7));
                LDMATRIX_X4(afr[mt][0], afr[mt][1], afr[mt][2], afr[mt][3], addr);
            }
            #pragma unroll
            for (int mt = 0; mt < 4; mt++)
                #pragma unroll
                for (int nt = 0; nt < 4; nt++)
                    MMA16816(acc[mt][nt][0], acc[mt][nt][1],
                             acc[mt][nt][2], acc[mt][nt][3],
                             afr[mt][0], afr[mt][1], afr[mt][2], afr[mt][3],
                             bfr[nt][0], bfr[nt][1]);
        }
        __syncthreads();
    }

    // epilogue (values are 32x the true q/k; cos is scale-invariant)
    float* C = (gz == 0) ? g_q : g_k;
    const int rowb = tm * 128 + wm * 64 + (lane >> 2);
    const int colb = tn * 128 + wn * 32 + 2 * (lane & 3);
    #pragma unroll
    for (int mt = 0; mt < 4; mt++) {
        #pragma unroll
        for (int nt = 0; nt < 4; nt++) {
            const size_t r0 = (size_t)(rowb + mt * 16) * Dn + colb + nt * 8;
            *(float2*)&C[r0]          = make_float2(acc[mt][nt][0], acc[mt][nt][1]);
            *(float2*)&C[r0 + 8 * Dn] = make_float2(acc[mt][nt][2], acc[mt][nt][3]);
        }
    }
    #undef LOAD_CHUNK
}

// ---------------------------------------------------------------------------
// Per-token props: p, b — all fp32 (exact fixup is the safety net).
// Flag |cos| < 1e-4 for fixup.
// ---------------------------------------------------------------------------
__global__ void props_kernel(float* __restrict__ out_p, float* __restrict__ out_b)
{
    const int t   = blockIdx.x;
    const int l   = t & (Ln - 1);
    const int tid = threadIdx.x;

    if (l == 0) {
        if (tid == 0) { out_p[t] = 1.0f; out_b[t] = 1.0f; }
        return;
    }
    const float4* qr = (const float4*)(g_q + (size_t)t * Dn);
    const float4* kr = (const float4*)(g_k + (size_t)(t - 1) * Dn);

    float sq = 0.f, sk = 0.f, sp = 0.f;
    #pragma unroll
    for (int it = 0; it < 2; it++) {
        const float4 qv = qr[tid + it * 128];
        const float4 kv = kr[tid + it * 128];
        sq = fmaf(qv.x, qv.x, sq); sq = fmaf(qv.y, qv.y, sq);
        sq = fmaf(qv.z, qv.z, sq); sq = fmaf(qv.w, qv.w, sq);
        sk = fmaf(kv.x, kv.x, sk); sk = fmaf(kv.y, kv.y, sk);
        sk = fmaf(kv.z, kv.z, sk); sk = fmaf(kv.w, kv.w, sk);
        sp = fmaf(qv.x, kv.x, sp); sp = fmaf(qv.y, kv.y, sp);
        sp = fmaf(qv.z, kv.z, sp); sp = fmaf(qv.w, kv.w, sp);
    }
    #pragma unroll
    for (int o = 16; o > 0; o >>= 1) {
        sq += __shfl_down_sync(0xffffffffu, sq, o);
        sk += __shfl_down_sync(0xffffffffu, sk, o);
        sp += __shfl_down_sync(0xffffffffu, sp, o);
    }
    __shared__ float sh[3][4];
    const int wid = tid >> 5, lane = tid & 31;
    if (lane == 0) { sh[0][wid] = sq; sh[1][wid] = sk; sh[2][wid] = sp; }
    __syncthreads();
    if (tid == 0) {
        const float SQ = sh[0][0] + sh[0][1] + sh[0][2] + sh[0][3];
        const float SK = sh[1][0] + sh[1][1] + sh[1][2] + sh[1][3];
        const float SP = sh[2][0] + sh[2][1] + sh[2][2] + sh[2][3];
        const float nq = fmaxf(sqrtf(SQ), 1e-12f);
        const float nk = fmaxf(sqrtf(SK), 1e-12f);
        const float cs = SP / (nq * nk);
        const float pv = 0.5f * (1.0f - cs);
        out_p[t] = pv;
        out_b[t] = (pv >= 0.5f) ? 1.0f : 0.0f;
        if (fabsf(cs) < 1e-4f) {
            const int ix = atomicAdd(&g_nfix, 1);
            if (ix < MAXFIX) {
                g_fix[ix] = t;
                g_fixacc[0][ix] = 0.0;
                g_fixacc[1][ix] = 0.0;
                g_fixacc[2][ix] = 0.0;
            }
        }
    }
}

// ---------------------------------------------------------------------------
// Fixup stage 1: exact partial sums for flagged tokens, coalesced reads.
// grid = (8 e-slices, MAXFIX token slots), 256 threads.
// ---------------------------------------------------------------------------
__global__ void fixup_partial_kernel(const float* __restrict__ x,
                                     const float* __restrict__ Wq,
                                     const float* __restrict__ Wk)
{
    const int nf = (g_nfix < MAXFIX) ? g_nfix : MAXFIX;
    const int it = blockIdx.y;
    if (it >= nf) return;
    const int t  = g_fix[it];
    const int sl = blockIdx.x;              // e-slice: 128 rows
    const int tid = threadIdx.x;
    const int lane = tid & 31, wrp = tid >> 5;

    __shared__ float xs[Dn], xp[Dn];
    for (int d = tid; d < Dn; d += 256) {
        xs[d] = x[(size_t)t * Dn + d];
        xp[d] = x[(size_t)(t - 1) * Dn + d];
    }
    __syncthreads();

    double sq = 0.0, sk = 0.0, sp = 0.0;
    #pragma unroll 1
    for (int i = 0; i < 16; i++) {
        const int e = sl * 128 + wrp * 16 + i;
        const float4* wq = (const float4*)(Wq + (size_t)e * Dn);
        const float4* wk = (const float4*)(Wk + (size_t)e * Dn);
        double qd = 0.0, kd = 0.0;
        #pragma unroll
        for (int jj = 0; jj < 8; jj++) {
            const int d4 = lane + jj * 32;
            const float4 w4 = wq[d4];
            const float4 v4 = wk[d4];
            const float4 a4 = *(const float4*)&xs[d4 * 4];
            const float4 b4 = *(const float4*)&xp[d4 * 4];
            float qp = a4.x * w4.x;
            qp = fmaf(a4.y, w4.y, qp); qp = fmaf(a4.z, w4.z, qp); qp = fmaf(a4.w, w4.w, qp);
            float kp = b4.x * v4.x;
            kp = fmaf(b4.y, v4.y, kp); kp = fmaf(b4.z, v4.z, kp); kp = fmaf(b4.w, v4.w, kp);
            qd += (double)qp;
            kd += (double)kp;
        }
        #pragma unroll
        for (int o = 16; o > 0; o >>= 1) {
            qd += __shfl_down_sync(0xffffffffu, qd, o);
            kd += __shfl_down_sync(0xffffffffu, kd, o);
        }
        if (lane == 0) { sq += qd * qd; sk += kd * kd; sp += qd * kd; }
    }
    if (lane == 0) {
        atomicAdd(&g_fixacc[0][it], sq);
        atomicAdd(&g_fixacc[1][it], sk);
        atomicAdd(&g_fixacc[2][it], sp);
    }
}

// Fixup stage 2: decide b from the exact sums.
__global__ void fixup_apply_kernel(float* __restrict__ out_b)
{
    const int i = threadIdx.x;
    const int nf = (g_nfix < MAXFIX) ? g_nfix : MAXFIX;
    if (i < nf) {
        const double cs = g_fixacc[2][i] / sqrt(g_fixacc[0][i] * g_fixacc[1][i]);
        out_b[g_fix[i]] = (cs <= 0.0) ? 1.0f : 0.0f;
    }
}

// ---------------------------------------------------------------------------
// Per-batch scan of b
// ---------------------------------------------------------------------------
__global__ void scan_kernel(const float* __restrict__ p_arr,
                            const float* __restrict__ b_arr,
                            float* __restrict__ P_down,
                            float* __restrict__ out_len)
{
    const int batch = blockIdx.x;
    const int tid   = threadIdx.x;
    const float* bb = b_arr + batch * Ln;
    const float* pp = p_arr + batch * Ln;
    const int base  = tid * 32;

    int    cnt  = 0;
    double sump = 0.0;
    #pragma unroll 8
    for (int jj = 0; jj < 32; jj++) {
        const float bv = bb[base + jj];
        cnt  += (bv > 0.5f) ? 1 : 0;
        sump += (double)pp[base + jj];
    }
    const int lane = tid & 31, wid = tid >> 5;
    int v = cnt;
    #pragma unroll
    for (int o = 1; o < 32; o <<= 1) {
        const int n = __shfl_up_sync(0xffffffffu, v, o);
        if (lane >= o) v += n;
    }
    __shared__ int wsum[8], woff[8], stotal;
    if (lane == 31) wsum[wid] = v;
    __syncthreads();
    if (tid == 0) {
        int s = 0;
        for (int w = 0; w < 8; w++) { woff[w] = s; s += wsum[w]; }
        stotal = s;
    }
    __syncthreads();

    int slot = woff[wid] + v - cnt;
    const int total = stotal;

    for (int jj = 0; jj < 32; jj++) {
        const float bv = bb[base + jj];
        if (bv > 0.5f) {
            const int l = base + jj;
            g_src[batch * Ln + slot]  = l;
            P_down[batch * Ln + slot] = pp[l];
            slot++;
        }
    }
    for (int s = total + tid; s < Ln; s += 256)
        P_down[batch * Ln + s] = 0.0f;

    #pragma unroll
    for (int o = 16; o > 0; o >>= 1)
        sump += __shfl_down_sync(0xffffffffu, sump, o);
    __shared__ double psh[8];
    if (lane == 0) psh[wid] = sump;
    __syncthreads();
    if (tid == 0) {
        double s = 0.0;
        for (int w = 0; w < 8; w++) s += psh[w];
        g_sumP[batch]  = s;
        g_len[batch]   = total;
        out_len[batch] = (float)total;
    }
}

// ---------------------------------------------------------------------------
// Gather x_down
// ---------------------------------------------------------------------------
__global__ void gather_kernel(const float* __restrict__ x, float* __restrict__ x_down)
{
    const int row   = blockIdx.x;
    const int batch = row >> 13;
    const int jj    = row & (Ln - 1);
    const int tid   = threadIdx.x;

    float4* dst = (float4*)(x_down + (size_t)row * Dn);
    if (jj < g_len[batch]) {
        const int src = g_src[row];
        const float4* s = (const float4*)(x + (size_t)(batch * Ln + src) * Dn);
        dst[tid] = s[tid];
    } else {
        dst[tid] = make_float4(0.f, 0.f, 0.f, 0.f);
    }
}

__global__ void finalize_kernel(float* __restrict__ o_loss)
{
    double sb = 0.0, sp = 0.0;
    for (int i = 0; i < Bn; i++) { sb += (double)g_len[i]; sp += g_sumP[i]; }
    const double F = sb / (double)BLn;
    const double G = sp / (double)BLn;
    const double N = 6.0;
    o_loss[0] = (float)(N / (N - 1.0) * ((N - 1.0) * F * G + (1.0 - F) * (1.0 - G)));
}

// ---------------------------------------------------------------------------
// Launch. Output layout (f32): x_down | P_down | b | p | lengths | ratio_loss
// ---------------------------------------------------------------------------
extern "C" void kernel_launch(void* const* d_in, const int* in_sizes, int n_in,
                              void* d_out, int out_size)
{
    const float* x  = (const float*)d_in[0];
    const float* Wq = (const float*)d_in[1];
    const float* Wk = (const float*)d_in[2];

    float* out    = (float*)d_out;
    float* o_xd   = out;
    float* o_P    = out + (size_t)BLn * Dn;
    float* o_b    = o_P + BLn;
    float* o_p    = o_b + BLn;
    float* o_len  = o_p + BLn;
    float* o_loss = o_len + Bn;

    cudaFuncSetAttribute(hgemm_kernel,
                         cudaFuncAttributeMaxDynamicSharedMemorySize, GEMM_SMEM);

    conv_w_kernel<<<(Dn * Dn / 4 + 255) / 256, 256>>>(Wq, 0, Dn * Dn / 4);
    conv_w_kernel<<<(Dn * Dn / 4 + 255) / 256, 256>>>(Wk, 1, Dn * Dn / 4);
    conv_x_kernel<<<(BLn * Dn / 4 + 255) / 256, 256>>>(x, BLn * Dn / 4);

    hgemm_kernel<<<dim3(8, 256, 2), 256, GEMM_SMEM>>>();

    props_kernel<<<BLn, 128>>>(o_p, o_b);
    fixup_partial_kernel<<<dim3(8, MAXFIX), 256>>>(x, Wq, Wk);
    fixup_apply_kernel<<<1, MAXFIX>>>(o_b);
    scan_kernel<<<Bn, 256>>>(o_p, o_b, o_P, o_len);
    gather_kernel<<<BLn, 256>>>(x, o_xd);
    finalize_kernel<<<1, 1>>>(o_loss);
}

// round 11
// speedup vs baseline: 3.9714x; 1.0284x over previous
#include <cuda_runtime.h>
#include <cuda_fp16.h>
#include <stdint.h>
#include <math.h>

// Problem shape (fixed)
#define Bn 4
#define Ln 8192
#define Dn 1024
#define BLn (Bn * Ln)   // 32768 tokens
#define MAXFIX 512

// ---------------------------------------------------------------------------
// Scratch (device globals)
// ---------------------------------------------------------------------------
__device__ __half g_qh[(size_t)BLn * Dn];           // 64 MB (32*q as fp16)
__device__ __half g_kh[(size_t)BLn * Dn];           // 64 MB (32*k as fp16)
__device__ __half g_xh[(size_t)BLn * Dn];           // 64 MB (x as fp16)
__device__ __half g_wh[2][(size_t)Dn * Dn];         // 4 MB  (32*Wq, 32*Wk fp16)
__device__ int    g_src[BLn];
__device__ int    g_len[Bn];
__device__ double g_sumP[Bn];
__device__ int    g_nfix;
__device__ int    g_fix[MAXFIX];
__device__ double g_fixacc[3][MAXFIX];

// ---------------------------------------------------------------------------
// helpers
// ---------------------------------------------------------------------------
__device__ __forceinline__ uint32_t cvta_shared_u32(const void* p) {
    uint32_t r;
    asm("{ .reg .u64 t; cvta.to.shared.u64 t, %1; cvt.u32.u64 %0, t; }"
        : "=r"(r) : "l"(p));
    return r;
}
#define LDMATRIX_X4(r0, r1, r2, r3, addr)                                  \
    asm volatile("ldmatrix.sync.aligned.m8n8.x4.shared.b16 {%0,%1,%2,%3}, [%4];" \
                 : "=r"(r0), "=r"(r1), "=r"(r2), "=r"(r3) : "r"(addr))
#define MMA16816(c0, c1, c2, c3, a0, a1, a2, a3, b0, b1)                   \
    asm volatile("mma.sync.aligned.m16n8k16.row.col.f32.f16.f16.f32 "      \
                 "{%0,%1,%2,%3}, {%4,%5,%6,%7}, {%8,%9}, {%0,%1,%2,%3};"   \
                 : "+f"(c0), "+f"(c1), "+f"(c2), "+f"(c3)                  \
                 : "r"(a0), "r"(a1), "r"(a2), "r"(a3), "r"(b0), "r"(b1))
#define CP_ASYNC16(saddr, gaddr)                                           \
    asm volatile("cp.async.cg.shared.global [%0], [%1], 16;"               \
                 :: "r"(saddr), "l"(gaddr))

// ---------------------------------------------------------------------------
// Converts: x -> fp16; W -> fp16 scaled by 32 (exact pow2; cos scale-inv).
// ---------------------------------------------------------------------------
__global__ void conv_x_kernel(const float* __restrict__ src, int n4)
{
    int i = blockIdx.x * blockDim.x + threadIdx.x;
    if (i >= n4) return;
    const float4 v = ((const float4*)src)[i];
    const __half2 h0 = __floats2half2_rn(v.x, v.y);
    const __half2 h1 = __floats2half2_rn(v.z, v.w);
    uint2 u;
    u.x = *(const uint32_t*)&h0;
    u.y = *(const uint32_t*)&h1;
    ((uint2*)&g_xh[0])[i] = u;
}

__global__ void conv_w_kernel(const float* __restrict__ src, int which, int n4)
{
    int i = blockIdx.x * blockDim.x + threadIdx.x;
    if (i >= n4) return;
    if (i == 0 && which == 0) g_nfix = 0;   // reset fixup list each replay
    const float4 v = ((const float4*)src)[i];
    const __half2 h0 = __floats2half2_rn(32.0f * v.x, 32.0f * v.y);
    const __half2 h1 = __floats2half2_rn(32.0f * v.z, 32.0f * v.w);
    uint2 u;
    u.x = *(const uint32_t*)&h0;
    u.y = *(const uint32_t*)&h1;
    ((uint2*)&g_wh[which][0])[i] = u;
}

// ---------------------------------------------------------------------------
// HMMA fp16 GEMM (single product): C = X * W^T, C stored as fp16.
// Tile 128x128, BK=64 (128B rows, XOR swizzle), 256 threads (8 warps 2x4),
// warp tile 64x32.  2 smem buffers, loads issued then wait_group 1.
// grid = (8 n-tiles, 256 m-tiles, 2 gemms).
// ---------------------------------------------------------------------------
#define SIDE_BYTES  16384                  // 128 rows * 128 B
#define BUF_BYTES   (2 * SIDE_BYTES)       // 32768 (A side + B side)
#define GEMM_SMEM   (2 * BUF_BYTES)        // 65536

// swizzled byte offset of 16B unit u (0..7) in row r (128B rows)
__device__ __forceinline__ uint32_t sw_off(int r, int u) {
    return (uint32_t)(128 * r + 16 * (u ^ (r & 7)));
}

__global__ __launch_bounds__(256, 2)
void hgemm_kernel()
{
    extern __shared__ char smem[];
    const uint32_t sbase = cvta_shared_u32(smem);

    const int tid  = threadIdx.x;
    const int wid  = tid >> 5;
    const int lane = tid & 31;
    const int wm   = wid & 1;          // 0..1 : 64-row half
    const int wn   = wid >> 1;         // 0..3 : 32-col quarter
    const int tn = blockIdx.x, tm = blockIdx.y, gz = blockIdx.z;

    const int j    = lane >> 3;        // ldmatrix matrix id 0..3
    const int rlow = lane & 7;

    int rA[4], rB[2];
    #pragma unroll
    for (int mt = 0; mt < 4; mt++)
        rA[mt] = wm * 64 + mt * 16 + (j & 1) * 8 + rlow;
    #pragma unroll
    for (int g = 0; g < 2; g++)
        rB[g] = wn * 32 + g * 16 + (j & 1) * 8 + rlow;
    const int jhi = j >> 1;

    float acc[4][4][4];
    #pragma unroll
    for (int mt = 0; mt < 4; mt++)
        #pragma unroll
        for (int nt = 0; nt < 4; nt++)
            #pragma unroll
            for (int e = 0; e < 4; e++) acc[mt][nt][e] = 0.0f;

    const char* xbase = (const char*)&g_xh[0] + (size_t)(tm * 128) * (Dn * 2);
    const char* wbase = (const char*)&g_wh[gz][0] + (size_t)(tn * 128) * (Dn * 2);

    // loader: 8 x 16B units per thread per chunk (2048 units total)
    int l_side[8], l_r[8], l_u[8];
    #pragma unroll
    for (int i = 0; i < 8; i++) {
        const int v    = tid + i * 256;
        const int side = v >= 1024;
        const int w    = v & 1023;
        l_side[i] = side;
        l_r[i]    = w >> 3;
        l_u[i]    = w & 7;
    }

    #define LOAD_CHUNK(buf, c)                                                   \
    do {                                                                         \
        const uint32_t bb = sbase + (buf) * BUF_BYTES;                           \
        _Pragma("unroll")                                                        \
        for (int i = 0; i < 8; i++) {                                            \
            const uint32_t sa = bb + l_side[i] * SIDE_BYTES +                    \
                                sw_off(l_r[i], l_u[i]);                          \
            const char* ga = (l_side[i] ? wbase : xbase) +                       \
                             (size_t)l_r[i] * (Dn * 2) + (c) * 128 + l_u[i] * 16;\
            CP_ASYNC16(sa, ga);                                                  \
        }                                                                        \
        asm volatile("cp.async.commit_group;");                                  \
    } while (0)

    const int NCH = Dn / 64;   // 16 chunks
    LOAD_CHUNK(0, 0);

    for (int c = 0; c < NCH; c++) {
        const int buf = c & 1;
        if (c + 1 < NCH) {
            LOAD_CHUNK(buf ^ 1, c + 1);
            asm volatile("cp.async.wait_group 1;");
        } else {
            asm volatile("cp.async.wait_group 0;");
        }
        __syncthreads();

        const uint32_t aB = sbase + buf * BUF_BYTES;
        const uint32_t bB = aB + SIDE_BYTES;

        #pragma unroll
        for (int ks = 0; ks < 4; ks++) {
            uint32_t bfr[4][2];
            #pragma unroll
            for (int g = 0; g < 2; g++) {
                uint32_t r0, r1, r2, r3;
                const uint32_t addr = bB + 128 * rB[g] +
                    16 * ((2 * ks + jhi) ^ (rB[g] & 7));
                LDMATRIX_X4(r0, r1, r2, r3, addr);
                bfr[2 * g + 0][0] = r0; bfr[2 * g + 0][1] = r2;
                bfr[2 * g + 1][0] = r1; bfr[2 * g + 1][1] = r3;
            }
            uint32_t afr[4][4];
            #pragma unroll
            for (int mt = 0; mt < 4; mt++) {
                const uint32_t addr = aB + 128 * rA[mt] +
                    16 * ((2 * ks + jhi) ^ (rA[mt] & 7));
                LDMATRIX_X4(afr[mt][0], afr[mt][1], afr[mt][2], afr[mt][3], addr);
            }
            #pragma unroll
            for (int mt = 0; mt < 4; mt++)
                #pragma unroll
                for (int nt = 0; nt < 4; nt++)
                    MMA16816(acc[mt][nt][0], acc[mt][nt][1],
                             acc[mt][nt][2], acc[mt][nt][3],
                             afr[mt][0], afr[mt][1], afr[mt][2], afr[mt][3],
                             bfr[nt][0], bfr[nt][1]);
        }
        __syncthreads();
    }

    // epilogue: store as fp16 (values are 32x true q/k; cos is scale-inv)
    __half* C = (gz == 0) ? g_qh : g_kh;
    const int rowb = tm * 128 + wm * 64 + (lane >> 2);
    const int colb = tn * 128 + wn * 32 + 2 * (lane & 3);
    #pragma unroll
    for (int mt = 0; mt < 4; mt++) {
        #pragma unroll
        for (int nt = 0; nt < 4; nt++) {
            const size_t r0 = (size_t)(rowb + mt * 16) * Dn + colb + nt * 8;
            const __half2 lo = __floats2half2_rn(acc[mt][nt][0], acc[mt][nt][1]);
            const __half2 hi = __floats2half2_rn(acc[mt][nt][2], acc[mt][nt][3]);
            *(__half2*)&C[r0]          = lo;
            *(__half2*)&C[r0 + 8 * Dn] = hi;
        }
    }
    #undef LOAD_CHUNK
}

// ---------------------------------------------------------------------------
// Per-token props: warp per token, fp16 q/k reads, fp32 math, shfl-only.
// 256 threads = 8 tokens/block; grid = BLn/8.
// ---------------------------------------------------------------------------
__global__ void props_kernel(float* __restrict__ out_p, float* __restrict__ out_b)
{
    const int t    = blockIdx.x * 8 + (threadIdx.x >> 5);
    const int lane = threadIdx.x & 31;

    if ((t & (Ln - 1)) == 0) {
        if (lane == 0) { out_p[t] = 1.0f; out_b[t] = 1.0f; }
        return;
    }
    const uint4* qr = (const uint4*)(g_qh + (size_t)t * Dn);
    const uint4* kr = (const uint4*)(g_kh + (size_t)(t - 1) * Dn);

    float sq = 0.f, sk = 0.f, sp = 0.f;
    #pragma unroll
    for (int i = 0; i < 4; i++) {
        const uint4 qu = qr[lane + i * 32];
        const uint4 ku = kr[lane + i * 32];
        const uint32_t qa[4] = {qu.x, qu.y, qu.z, qu.w};
        const uint32_t ka[4] = {ku.x, ku.y, ku.z, ku.w};
        #pragma unroll
        for (int c = 0; c < 4; c++) {
            const float2 qf = __half22float2(*(const __half2*)&qa[c]);
            const float2 kf = __half22float2(*(const __half2*)&ka[c]);
            sq = fmaf(qf.x, qf.x, sq); sq = fmaf(qf.y, qf.y, sq);
            sk = fmaf(kf.x, kf.x, sk); sk = fmaf(kf.y, kf.y, sk);
            sp = fmaf(qf.x, kf.x, sp); sp = fmaf(qf.y, kf.y, sp);
        }
    }
    #pragma unroll
    for (int o = 16; o > 0; o >>= 1) {
        sq += __shfl_down_sync(0xffffffffu, sq, o);
        sk += __shfl_down_sync(0xffffffffu, sk, o);
        sp += __shfl_down_sync(0xffffffffu, sp, o);
    }
    if (lane == 0) {
        const float nq = fmaxf(sqrtf(sq), 1e-12f);
        const float nk = fmaxf(sqrtf(sk), 1e-12f);
        const float cs = sp / (nq * nk);
        const float pv = 0.5f * (1.0f - cs);
        out_p[t] = pv;
        out_b[t] = (pv >= 0.5f) ? 1.0f : 0.0f;
        if (fabsf(cs) < 1e-4f) {
            const int ix = atomicAdd(&g_nfix, 1);
            if (ix < MAXFIX) {
                g_fix[ix] = t;
                g_fixacc[0][ix] = 0.0;
                g_fixacc[1][ix] = 0.0;
                g_fixacc[2][ix] = 0.0;
            }
        }
    }
}

// ---------------------------------------------------------------------------
// Fixup stage 1: exact partial sums for flagged tokens (f32 inputs, fp64 acc).
// grid = (8 e-slices, MAXFIX token slots), 256 threads.
// ---------------------------------------------------------------------------
__global__ void fixup_partial_kernel(const float* __restrict__ x,
                                     const float* __restrict__ Wq,
                                     const float* __restrict__ Wk)
{
    const int nf = (g_nfix < MAXFIX) ? g_nfix : MAXFIX;
    const int it = blockIdx.y;
    if (it >= nf) return;
    const int t  = g_fix[it];
    const int sl = blockIdx.x;              // e-slice: 128 rows
    const int tid = threadIdx.x;
    const int lane = tid & 31, wrp = tid >> 5;

    __shared__ float xs[Dn], xp[Dn];
    for (int d = tid; d < Dn; d += 256) {
        xs[d] = x[(size_t)t * Dn + d];
        xp[d] = x[(size_t)(t - 1) * Dn + d];
    }
    __syncthreads();

    double sq = 0.0, sk = 0.0, sp = 0.0;
    #pragma unroll 1
    for (int i = 0; i < 16; i++) {
        const int e = sl * 128 + wrp * 16 + i;
        const float4* wq = (const float4*)(Wq + (size_t)e * Dn);
        const float4* wk = (const float4*)(Wk + (size_t)e * Dn);
        double qd = 0.0, kd = 0.0;
        #pragma unroll
        for (int jj = 0; jj < 8; jj++) {
            const int d4 = lane + jj * 32;
            const float4 w4 = wq[d4];
            const float4 v4 = wk[d4];
            const float4 a4 = *(const float4*)&xs[d4 * 4];
            const float4 b4 = *(const float4*)&xp[d4 * 4];
            float qp = a4.x * w4.x;
            qp = fmaf(a4.y, w4.y, qp); qp = fmaf(a4.z, w4.z, qp); qp = fmaf(a4.w, w4.w, qp);
            float kp = b4.x * v4.x;
            kp = fmaf(b4.y, v4.y, kp); kp = fmaf(b4.z, v4.z, kp); kp = fmaf(b4.w, v4.w, kp);
            qd += (double)qp;
            kd += (double)kp;
        }
        #pragma unroll
        for (int o = 16; o > 0; o >>= 1) {
            qd += __shfl_down_sync(0xffffffffu, qd, o);
            kd += __shfl_down_sync(0xffffffffu, kd, o);
        }
        if (lane == 0) { sq += qd * qd; sk += kd * kd; sp += qd * kd; }
    }
    if (lane == 0) {
        atomicAdd(&g_fixacc[0][it], sq);
        atomicAdd(&g_fixacc[1][it], sk);
        atomicAdd(&g_fixacc[2][it], sp);
    }
}

// Fixup stage 2: decide b from the exact sums.
__global__ void fixup_apply_kernel(float* __restrict__ out_b)
{
    const int i = threadIdx.x;
    const int nf = (g_nfix < MAXFIX) ? g_nfix : MAXFIX;
    if (i < nf) {
        const double cs = g_fixacc[2][i] / sqrt(g_fixacc[0][i] * g_fixacc[1][i]);
        out_b[g_fix[i]] = (cs <= 0.0) ? 1.0f : 0.0f;
    }
}

// ---------------------------------------------------------------------------
// Per-batch scan of b
// ---------------------------------------------------------------------------
__global__ void scan_kernel(const float* __restrict__ p_arr,
                            const float* __restrict__ b_arr,
                            float* __restrict__ P_down,
                            float* __restrict__ out_len)
{
    const int batch = blockIdx.x;
    const int tid   = threadIdx.x;
    const float* bb = b_arr + batch * Ln;
    const float* pp = p_arr + batch * Ln;
    const int base  = tid * 32;

    int    cnt  = 0;
    double sump = 0.0;
    #pragma unroll 8
    for (int jj = 0; jj < 32; jj++) {
        const float bv = bb[base + jj];
        cnt  += (bv > 0.5f) ? 1 : 0;
        sump += (double)pp[base + jj];
    }
    const int lane = tid & 31, wid = tid >> 5;
    int v = cnt;
    #pragma unroll
    for (int o = 1; o < 32; o <<= 1) {
        const int n = __shfl_up_sync(0xffffffffu, v, o);
        if (lane >= o) v += n;
    }
    __shared__ int wsum[8], woff[8], stotal;
    if (lane == 31) wsum[wid] = v;
    __syncthreads();
    if (tid == 0) {
        int s = 0;
        for (int w = 0; w < 8; w++) { woff[w] = s; s += wsum[w]; }
        stotal = s;
    }
    __syncthreads();

    int slot = woff[wid] + v - cnt;
    const int total = stotal;

    for (int jj = 0; jj < 32; jj++) {
        const float bv = bb[base + jj];
        if (bv > 0.5f) {
            const int l = base + jj;
            g_src[batch * Ln + slot]  = l;
            P_down[batch * Ln + slot] = pp[l];
            slot++;
        }
    }
    for (int s = total + tid; s < Ln; s += 256)
        P_down[batch * Ln + s] = 0.0f;

    #pragma unroll
    for (int o = 16; o > 0; o >>= 1)
        sump += __shfl_down_sync(0xffffffffu, sump, o);
    __shared__ double psh[8];
    if (lane == 0) psh[wid] = sump;
    __syncthreads();
    if (tid == 0) {
        double s = 0.0;
        for (int w = 0; w < 8; w++) s += psh[w];
        g_sumP[batch]  = s;
        g_len[batch]   = total;
        out_len[batch] = (float)total;
    }
}

// ---------------------------------------------------------------------------
// Gather x_down
// ---------------------------------------------------------------------------
__global__ void gather_kernel(const float* __restrict__ x, float* __restrict__ x_down)
{
    const int row   = blockIdx.x;
    const int batch = row >> 13;
    const int jj    = row & (Ln - 1);
    const int tid   = threadIdx.x;

    float4* dst = (float4*)(x_down + (size_t)row * Dn);
    if (jj < g_len[batch]) {
        const int src = g_src[row];
        const float4* s = (const float4*)(x + (size_t)(batch * Ln + src) * Dn);
        dst[tid] = s[tid];
    } else {
        dst[tid] = make_float4(0.f, 0.f, 0.f, 0.f);
    }
}

__global__ void finalize_kernel(float* __restrict__ o_loss)
{
    double sb = 0.0, sp = 0.0;
    for (int i = 0; i < Bn; i++) { sb += (double)g_len[i]; sp += g_sumP[i]; }
    const double F = sb / (double)BLn;
    const double G = sp / (double)BLn;
    const double N = 6.0;
    o_loss[0] = (float)(N / (N - 1.0) * ((N - 1.0) * F * G + (1.0 - F) * (1.0 - G)));
}

// ---------------------------------------------------------------------------
// Launch. Output layout (f32): x_down | P_down | b | p | lengths | ratio_loss
// ---------------------------------------------------------------------------
extern "C" void kernel_launch(void* const* d_in, const int* in_sizes, int n_in,
                              void* d_out, int out_size)
{
    const float* x  = (const float*)d_in[0];
    const float* Wq = (const float*)d_in[1];
    const float* Wk = (const float*)d_in[2];

    float* out    = (float*)d_out;
    float* o_xd   = out;
    float* o_P    = out + (size_t)BLn * Dn;
    float* o_b    = o_P + BLn;
    float* o_p    = o_b + BLn;
    float* o_len  = o_p + BLn;
    float* o_loss = o_len + Bn;

    cudaFuncSetAttribute(hgemm_kernel,
                         cudaFuncAttributeMaxDynamicSharedMemorySize, GEMM_SMEM);

    conv_w_kernel<<<(Dn * Dn / 4 + 255) / 256, 256>>>(Wq, 0, Dn * Dn / 4);
    conv_w_kernel<<<(Dn * Dn / 4 + 255) / 256, 256>>>(Wk, 1, Dn * Dn / 4);
    conv_x_kernel<<<(BLn * Dn / 4 + 255) / 256, 256>>>(x, BLn * Dn / 4);

    hgemm_kernel<<<dim3(8, 256, 2), 256, GEMM_SMEM>>>();

    props_kernel<<<BLn / 8, 256>>>(o_p, o_b);
    fixup_partial_kernel<<<dim3(8, MAXFIX), 256>>>(x, Wq, Wk);
    fixup_apply_kernel<<<1, MAXFIX>>>(o_b);
    scan_kernel<<<Bn, 256>>>(o_p, o_b, o_P, o_len);
    gather_kernel<<<BLn, 256>>>(x, o_xd);
    finalize_kernel<<<1, 1>>>(o_loss);
}